// round 9
// baseline (speedup 1.0000x reference)
#include <cuda_runtime.h>
#include <cuda_bf16.h>
#include <math.h>

#define Bz 16
#define Sz 512
#define Hz 512
#define Vz 10000
#define Gz 2048
#define HP 1032

// ---- scratch (static device globals) ----
__device__ float g_emb [Bz*Sz*Hz];
__device__ float g_xproj[Bz*Sz*Gz];
__device__ float g_hs1 [Bz*Sz*Hz];
__device__ float g_hid [Bz*Sz*128];
__device__ __align__(16) __nv_bfloat16 g_h0hi[4][Bz*Hz];
__device__ __align__(16) __nv_bfloat16 g_h0lo[4][Bz*Hz];
__device__ __align__(16) __nv_bfloat16 g_h1hi[4][Bz*Hz];
__device__ __align__(16) __nv_bfloat16 g_h1lo[4][Bz*Hz];
__device__ unsigned g_sync[64];   // ctr0 @0, ctr1 @32

// ------------------------------------------------------------------
__global__ void reset_kernel() {
    if (threadIdx.x < 64) g_sync[threadIdx.x] = 0u;
}

__global__ void embed_kernel(const int* __restrict__ src,
                             const float* __restrict__ w_emb,
                             const float* __restrict__ b_emb)
{
    int idx = blockIdx.x * 256 + threadIdx.x;
    if (idx >= Bz*Sz*Hz) return;
    int h  = idx & (Hz-1);
    int bs = idx >> 9;
    int v  = src[bs];
    g_emb[idx] = w_emb[h*Vz + v] + b_emb[h];
}

// ------------------------------------------------------------------
// tf32 tensor-core GEMM (proven R4, unchanged).
__device__ __forceinline__ unsigned f2tf(float f) {
    unsigned u;
    asm("cvt.rna.tf32.f32 %0, %1;" : "=r"(u) : "f"(f));
    return u;
}
__device__ __forceinline__ void mma_tf32(float* d, const unsigned* a,
                                         const unsigned* b) {
    asm("mma.sync.aligned.m16n8k8.row.col.f32.tf32.tf32.f32 "
        "{%0,%1,%2,%3}, {%4,%5,%6,%7}, {%8,%9}, {%0,%1,%2,%3};"
        : "+f"(d[0]), "+f"(d[1]), "+f"(d[2]), "+f"(d[3])
        : "r"(a[0]), "r"(a[1]), "r"(a[2]), "r"(a[3]),
          "r"(b[0]), "r"(b[1]));
}

__global__ void __launch_bounds__(256)
gemm_tf32(const float* __restrict__ A, const float* __restrict__ B,
          const float* __restrict__ bias, const float* __restrict__ bias2,
          float* __restrict__ C, int M, int N, int K, int relu)
{
    __shared__ unsigned As[8*4*4*32];
    __shared__ unsigned Bs[16*4*2*32];

    const int tid = threadIdx.x;
    const int n0 = blockIdx.x * 128;
    const int m0 = blockIdx.y * 128;

    const int lm = tid >> 1;
    const int lk = (tid & 1) * 16;
    const float* Ap = A + (size_t)(m0 + lm) * K + lk;
    const float* Bp = B + (size_t)(n0 + lm) * K + lk;
    const bool bval = (n0 + lm) < N;

    const int warp = tid >> 5;
    const int lane = tid & 31;
    const int wm = warp >> 2;
    const int wn = warp & 3;

    float acc[4][4][4];
#pragma unroll
    for (int i = 0; i < 4; i++)
#pragma unroll
        for (int j = 0; j < 4; j++)
#pragma unroll
            for (int r = 0; r < 4; r++) acc[i][j][r] = 0.f;

    float4 a_r[4], b_r[4];
    const float4 z4 = make_float4(0.f, 0.f, 0.f, 0.f);
#pragma unroll
    for (int j = 0; j < 4; j++) {
        a_r[j] = *(const float4*)(Ap + 4*j);
        b_r[j] = bval ? *(const float4*)(Bp + 4*j) : z4;
    }

    const int mt_s = lm >> 4, r_s = lm & 15;
    const int nt_s = lm >> 3, ln_s = lm & 7;
    const int nch = K >> 5;

    for (int ch = 0; ch < nch; ch++) {
        __syncthreads();
#pragma unroll
        for (int j = 0; j < 4; j++) {
            int kc = lk + 4*j;
            int ks = kc >> 3;
            int cr = (kc & 7) >> 2;
            uint4 av = make_uint4(f2tf(a_r[j].x), f2tf(a_r[j].y),
                                  f2tf(a_r[j].z), f2tf(a_r[j].w));
            *(uint4*)&As[(((mt_s*4 + ks)*4) + cr*2 + (r_s >> 3))*32 + (r_s & 7)*4] = av;
            uint4 bv = make_uint4(f2tf(b_r[j].x), f2tf(b_r[j].y),
                                  f2tf(b_r[j].z), f2tf(b_r[j].w));
            *(uint4*)&Bs[(((nt_s*4 + ks)*2) + cr)*32 + ln_s*4] = bv;
        }
        __syncthreads();

        if (ch + 1 < nch) {
            const float* ap = Ap + (ch + 1)*32;
            const float* bp = Bp + (ch + 1)*32;
#pragma unroll
            for (int j = 0; j < 4; j++) {
                a_r[j] = *(const float4*)(ap + 4*j);
                b_r[j] = bval ? *(const float4*)(bp + 4*j) : z4;
            }
        }

#pragma unroll
        for (int ks = 0; ks < 4; ks++) {
            unsigned af[4][4];
#pragma unroll
            for (int mi = 0; mi < 4; mi++) {
                int base = (((wm*4 + mi)*4 + ks)*4)*32 + lane;
                af[mi][0] = As[base];
                af[mi][1] = As[base + 32];
                af[mi][2] = As[base + 64];
                af[mi][3] = As[base + 96];
            }
#pragma unroll
            for (int ni = 0; ni < 4; ni++) {
                int bb = (((wn*4 + ni)*4 + ks)*2)*32 + lane;
                unsigned bf[2] = { Bs[bb], Bs[bb + 32] };
#pragma unroll
                for (int mi = 0; mi < 4; mi++)
                    mma_tf32(acc[mi][ni], af[mi], bf);
            }
        }
    }

    const int g  = lane >> 2;
    const int tg = lane & 3;
#pragma unroll
    for (int ni = 0; ni < 4; ni++) {
        int ncol = n0 + wn*32 + ni*8 + tg*2;
        if (ncol < N) {
            float bb0 = bias[ncol]   + (bias2 ? bias2[ncol]   : 0.f);
            float bb1 = bias[ncol+1] + (bias2 ? bias2[ncol+1] : 0.f);
#pragma unroll
            for (int mi = 0; mi < 4; mi++) {
                int mrow = m0 + wm*64 + mi*16 + g;
                float2 v0 = make_float2(acc[mi][ni][0] + bb0,
                                        acc[mi][ni][1] + bb1);
                float2 v1 = make_float2(acc[mi][ni][2] + bb0,
                                        acc[mi][ni][3] + bb1);
                if (relu) {
                    v0.x = fmaxf(v0.x, 0.f); v0.y = fmaxf(v0.y, 0.f);
                    v1.x = fmaxf(v1.x, 0.f); v1.y = fmaxf(v1.y, 0.f);
                }
                *(float2*)(C + (size_t)mrow * N + ncol)       = v0;
                *(float2*)(C + (size_t)(mrow + 8) * N + ncol) = v1;
            }
        }
    }
}

// ------------------------------------------------------------------
__device__ __forceinline__ void poll_ge(unsigned* p, unsigned tgt) {
    unsigned v;
    do {
        asm volatile("ld.acquire.gpu.global.u32 %0, [%1];"
                     : "=r"(v) : "l"(p) : "memory");
    } while (v < tgt);
}
__device__ __forceinline__ void arrive(unsigned* p) {
    asm volatile("red.release.gpu.global.add.u32 [%0], 1;"
                 :: "l"(p) : "memory");
}

__device__ __forceinline__ unsigned pack_bf2(__nv_bfloat16 a, __nv_bfloat16 b) {
    return ((unsigned)__bfloat16_as_ushort(b) << 16) | __bfloat16_as_ushort(a);
}
__device__ __forceinline__ void mma_bf16(float* d, const unsigned* a,
                                         unsigned b0, unsigned b1) {
    asm("mma.sync.aligned.m16n8k16.row.col.f32.bf16.bf16.f32 "
        "{%0,%1,%2,%3}, {%4,%5,%6,%7}, {%8,%9}, {%0,%1,%2,%3};"
        : "+f"(d[0]), "+f"(d[1]), "+f"(d[2]), "+f"(d[3])
        : "r"(a[0]), "r"(a[1]), "r"(a[2]), "r"(a[3]), "r"(b0), "r"(b1));
}
__device__ __forceinline__ void ldsm_x4(unsigned& r0, unsigned& r1,
                                        unsigned& r2, unsigned& r3,
                                        unsigned addr) {
    asm volatile("ldmatrix.sync.aligned.m8n8.x4.shared.b16 {%0,%1,%2,%3}, [%4];"
                 : "=r"(r0), "=r"(r1), "=r"(r2), "=r"(r3) : "r"(addr));
}
__device__ __forceinline__ unsigned smem_u32(const void* p) {
    return (unsigned)__cvta_generic_to_shared(p);
}
__device__ __forceinline__ float fsig(float x) {
    return __fdividef(1.f, 1.f + __expf(-x));
}
__device__ __forceinline__ float ftanh(float x) {
    float xc = fminf(fmaxf(x, -15.f), 15.f);
    float e = __expf(2.f * xc);
    return __fdividef(e - 1.f, e + 1.f);
}

// ------------------------------------------------------------------
// Fused 2-layer wavefront LSTM. 96 CTAs (32 L0 / 64 L1). Distinct-k warps
// (no redundant B reads), reg A-frags, ldmatrix B, fast activations,
// two-phase L1 staging, decoupled counters + 4-deep h buffers.
__global__ void __launch_bounds__(256)
lstm_fused(const float* __restrict__ xproj,
           const float* __restrict__ w_hh0,
           const float* __restrict__ w_ih1,
           const float* __restrict__ w_hh1,
           const float* __restrict__ b_ih1,
           const float* __restrict__ b_hh1,
           float* __restrict__ hs1)
{
    extern __shared__ __align__(16) unsigned char dyn[];
    __nv_bfloat16* Hhi_s = (__nv_bfloat16*)dyn;            // [16][HP]
    __nv_bfloat16* Hlo_s = Hhi_s + 16*HP;
    unsigned char* uni = dyn + 2*16*HP*2;                  // 128KB union
    float* w_stage = (float*)uni;                          // init only
    float* part  = (float*)uni;                            // [8][1024]
    float* act_s = part + 8192;                            // [1024]
    float* c_s   = act_s + 1024;                           // [256]

    const int tid  = threadIdx.x;
    const int bid  = blockIdx.x;
    const bool is0 = bid < 32;
    const int u0   = is0 ? bid*16 : (bid-32)*8;
    const int warp = tid >> 5;
    const int lane = tid & 31;
    const int g    = lane >> 2;
    const int tg   = lane & 3;
    unsigned* ctr0 = g_sync;
    unsigned* ctr1 = g_sync + 32;

    const int Kw = is0 ? 512 : 1024;

    // ---- stage weights coalesced into SMEM ----
    for (int idx4 = tid; idx4 < 8192; idx4 += 256) {
        int row, k;
        if (is0) { row = idx4 >> 7; k = (idx4 & 127) * 4; }
        else     { row = idx4 >> 8; k = (idx4 & 255) * 4; }
        const float* W;
        int gate, koff;
        if (is0) {
            gate = (row >> 4)*Hz + u0 + (row & 15);
            W = w_hh0; koff = k;
        } else {
            gate = (row >> 3)*Hz + u0 + (row & 7);
            if (k < Hz) { W = w_ih1; koff = k; }
            else        { W = w_hh1; koff = k - Hz; }
        }
        *(float4*)(w_stage + row*Kw + k) =
            *(const float4*)(W + (size_t)gate*Hz + koff);
    }
    __syncthreads();

    // ---- A fragments -> registers (split-bf16), distinct-k per warp ----
    // L0: warp k-range [warp*64, +64), 4 kk, all 4 mt  -> Ahi[mt*4+kk]
    // L1: warp k-range [warp*128,+128), 8 kk, both mt  -> Ahi[mt*8+kk]
    unsigned Ahi[16][4], Alo[16][4];
    {
        const int nmt = is0 ? 4 : 2;
        const int nkk = is0 ? 4 : 8;
        const int kbase = warp * (is0 ? 64 : 128);
        for (int mt2 = 0; mt2 < nmt; mt2++)
            for (int kk = 0; kk < nkk; kk++) {
                int fi = mt2*nkk + kk;
#pragma unroll
                for (int r = 0; r < 4; r++) {
                    int row = mt2*16 + g + (r & 1)*8;
                    int k   = kbase + kk*16 + 2*tg + (r >> 1)*8;
                    float w0 = w_stage[row*Kw + k];
                    float w1 = w_stage[row*Kw + k + 1];
                    __nv_bfloat16 h0 = __float2bfloat16(w0);
                    __nv_bfloat16 h1 = __float2bfloat16(w1);
                    __nv_bfloat16 l0 = __float2bfloat16(w0 - __bfloat162float(h0));
                    __nv_bfloat16 l1 = __float2bfloat16(w1 - __bfloat162float(h1));
                    Ahi[fi][r] = pack_bf2(h0, h1);
                    Alo[fi][r] = pack_bf2(l0, l1);
                }
            }
    }
    __syncthreads();   // all w_stage reads done before part/c_s writes

    // ---- ldmatrix lane addressing (B frags) ----
    const int mrow = lane >> 3, rr = lane & 7;
    const int nn   = ((mrow >> 1) << 3) + rr;
    const int kof  = (mrow & 1) * 8;
    const unsigned bhi_base = smem_u32(Hhi_s) + (nn*HP + kof)*2;
    const unsigned blo_base = bhi_base + 16*HP*2;

    // ---- init state + base (xproj / bias) ----
    float base_r[4];
    const __nv_bfloat16 zb = __float2bfloat16(0.f);
    if (is0) {
        c_s[tid] = 0.f;
        int u = u0 + (tid >> 4), b = tid & 15;
        g_h0hi[3][b*Hz + u] = zb;
        g_h0lo[3][b*Hz + u] = zb;
#pragma unroll
        for (int j = 0; j < 4; j++) {
            int idx = tid + 256*j;
            int lg = idx >> 4, b2 = idx & 15;
            int gate = (lg >> 4)*Hz + u0 + (lg & 15);
            base_r[j] = xproj[((size_t)(b2 << 9))*Gz + gate];
        }
    } else {
        if (tid < 128) {
            c_s[tid] = 0.f;
            int u = u0 + (tid >> 4), b = tid & 15;
            g_h1hi[3][b*Hz + u] = zb;
            g_h1lo[3][b*Hz + u] = zb;
        }
#pragma unroll
        for (int j = 0; j < 2; j++) {
            int idx = tid + 256*j;
            int lg = idx >> 4;
            int gate = (lg >> 3)*Hz + u0 + (lg & 7);
            base_r[j] = b_ih1[gate] + b_hh1[gate];
        }
    }
    __syncthreads();
    if (tid == 0) arrive(is0 ? ctr0 : ctr1);

    if (is0) {
        // ============ LAYER 0: rounds r = 0..511 ============
        for (int r = 0; r < Sz; r++) {
            if (tid < 2) {
                unsigned* p  = (tid == 0) ? ctr0 : ctr1;
                unsigned tgt = (tid == 0) ? 32u*(r+1)
                             : (r >= 3 ? 64u*(r-2) : 0u);
                if (tgt) poll_ge(p, tgt);
            }
            __syncthreads();

            {   // stage h0_{r-1}
                const uint4* ghi = (const uint4*)g_h0hi[(r+3)&3];
                const uint4* glo = (const uint4*)g_h0lo[(r+3)&3];
#pragma unroll
                for (int i = 0; i < 4; i++) {
                    int idx = tid + 256*i;
                    int b = idx >> 6, uo = (idx & 63)*8;
                    uint4 vh = __ldcg(ghi + idx);
                    uint4 vl = __ldcg(glo + idx);
                    *(uint4*)(Hhi_s + b*HP + uo) = vh;
                    *(uint4*)(Hlo_s + b*HP + uo) = vl;
                }
            }
            float nxt[4];
            {
                int tn = (r + 1 < Sz) ? r + 1 : r;
#pragma unroll
                for (int j = 0; j < 4; j++) {
                    int idx = tid + 256*j;
                    int lg = idx >> 4, b2 = idx & 15;
                    int gate = (lg >> 4)*Hz + u0 + (lg & 15);
                    nxt[j] = xproj[((size_t)((b2 << 9) | tn))*Gz + gate];
                }
            }
            __syncthreads();

            float acc[4][2][4];
#pragma unroll
            for (int m2 = 0; m2 < 4; m2++)
#pragma unroll
                for (int n2 = 0; n2 < 2; n2++)
#pragma unroll
                    for (int q = 0; q < 4; q++) acc[m2][n2][q] = 0.f;

#pragma unroll
            for (int kk = 0; kk < 4; kk++) {
                int ks = warp*4 + kk;
                unsigned bh0,bh1,bh2,bh3, bl0,bl1,bl2,bl3;
                ldsm_x4(bh0,bh1,bh2,bh3, bhi_base + ks*32);
                ldsm_x4(bl0,bl1,bl2,bl3, blo_base + ks*32);
#pragma unroll
                for (int m2 = 0; m2 < 4; m2++) {
                    int fi = m2*4 + kk;
                    mma_bf16(acc[m2][0], Ahi[fi], bh0, bh1);
                    mma_bf16(acc[m2][1], Ahi[fi], bh2, bh3);
                    mma_bf16(acc[m2][0], Ahi[fi], bl0, bl1);
                    mma_bf16(acc[m2][1], Ahi[fi], bl2, bl3);
                    mma_bf16(acc[m2][0], Alo[fi], bh0, bh1);
                    mma_bf16(acc[m2][1], Alo[fi], bh2, bh3);
                }
            }
            {
                float* pw = part + warp*1024;
#pragma unroll
                for (int m2 = 0; m2 < 4; m2++) {
                    int r0 = m2*16 + g, r1 = r0 + 8;
                    *(float2*)&pw[r0*16 + 2*tg]     = make_float2(acc[m2][0][0], acc[m2][0][1]);
                    *(float2*)&pw[r1*16 + 2*tg]     = make_float2(acc[m2][0][2], acc[m2][0][3]);
                    *(float2*)&pw[r0*16 + 8 + 2*tg] = make_float2(acc[m2][1][0], acc[m2][1][1]);
                    *(float2*)&pw[r1*16 + 8 + 2*tg] = make_float2(acc[m2][1][2], acc[m2][1][3]);
                }
            }
            __syncthreads();

#pragma unroll
            for (int j = 0; j < 4; j++) {
                int idx = tid + 256*j;
                float s = base_r[j];
#pragma unroll
                for (int w = 0; w < 8; w++) s += part[w*1024 + idx];
                int gt = idx >> 8;
                act_s[idx] = (gt == 2) ? ftanh(s) : fsig(s);
            }
            __syncthreads();

            {
                float iv = act_s[tid];
                float fv = act_s[256 + tid];
                float gv = act_s[512 + tid];
                float ov = act_s[768 + tid];
                float c = fv*c_s[tid] + iv*gv;
                c_s[tid] = c;
                float h = ov*ftanh(c);
                __nv_bfloat16 hh = __float2bfloat16(h);
                __nv_bfloat16 hl = __float2bfloat16(h - __bfloat162float(hh));
                int u = u0 + (tid >> 4), b = tid & 15;
                g_h0hi[r & 3][b*Hz + u] = hh;
                g_h0lo[r & 3][b*Hz + u] = hl;
            }
#pragma unroll
            for (int j = 0; j < 4; j++) base_r[j] = nxt[j];
            __syncthreads();
            if (tid == 0) arrive(ctr0);
        }
    } else {
        // ============ LAYER 1: rounds r = 1..512 ============
        for (int r = 1; r <= Sz; r++) {
            const int t = r - 1;
            // phase 1: own-layer h1_{t-1} (ready after our previous round)
            if (tid == 0) poll_ge(ctr1, 64u*r);
            __syncthreads();
            {
                const uint4* g1h = (const uint4*)g_h1hi[(t+3) & 3];
                const uint4* g1l = (const uint4*)g_h1lo[(t+3) & 3];
#pragma unroll
                for (int i = 0; i < 4; i++) {
                    int idx = tid + 256*i;
                    int b = idx >> 6, uo = (idx & 63)*8;
                    uint4 wh = __ldcg(g1h + idx);
                    uint4 wl = __ldcg(g1l + idx);
                    *(uint4*)(Hhi_s + b*HP + 512 + uo) = wh;
                    *(uint4*)(Hlo_s + b*HP + 512 + uo) = wl;
                }
            }
            // phase 2: wait for L0's h0_t, then stage it
            if (tid == 0) poll_ge(ctr0, 32u*(r+1));
            __syncthreads();
            {
                const uint4* g0h = (const uint4*)g_h0hi[t & 3];
                const uint4* g0l = (const uint4*)g_h0lo[t & 3];
#pragma unroll
                for (int i = 0; i < 4; i++) {
                    int idx = tid + 256*i;
                    int b = idx >> 6, uo = (idx & 63)*8;
                    uint4 vh = __ldcg(g0h + idx);
                    uint4 vl = __ldcg(g0l + idx);
                    *(uint4*)(Hhi_s + b*HP + uo) = vh;
                    *(uint4*)(Hlo_s + b*HP + uo) = vl;
                }
            }
            __syncthreads();

            float accM[2][2][4], accC[2][2][4];
#pragma unroll
            for (int m2 = 0; m2 < 2; m2++)
#pragma unroll
                for (int n2 = 0; n2 < 2; n2++)
#pragma unroll
                    for (int q = 0; q < 4; q++) {
                        accM[m2][n2][q] = 0.f;
                        accC[m2][n2][q] = 0.f;
                    }

#pragma unroll
            for (int kk = 0; kk < 8; kk++) {
                int ks = warp*8 + kk;
                unsigned bh0,bh1,bh2,bh3, bl0,bl1,bl2,bl3;
                ldsm_x4(bh0,bh1,bh2,bh3, bhi_base + ks*32);
                ldsm_x4(bl0,bl1,bl2,bl3, blo_base + ks*32);
#pragma unroll
                for (int m2 = 0; m2 < 2; m2++) {
                    int fi = m2*8 + kk;
                    mma_bf16(accM[m2][0], Ahi[fi], bh0, bh1);
                    mma_bf16(accM[m2][1], Ahi[fi], bh2, bh3);
                    mma_bf16(accC[m2][0], Ahi[fi], bl0, bl1);
                    mma_bf16(accC[m2][1], Ahi[fi], bl2, bl3);
                    mma_bf16(accC[m2][0], Alo[fi], bh0, bh1);
                    mma_bf16(accC[m2][1], Alo[fi], bh2, bh3);
                }
            }
            {
                float* pw = part + warp*512;
#pragma unroll
                for (int m2 = 0; m2 < 2; m2++) {
                    int r0 = m2*16 + g, r1 = r0 + 8;
                    *(float2*)&pw[r0*16 + 2*tg] =
                        make_float2(accM[m2][0][0] + accC[m2][0][0],
                                    accM[m2][0][1] + accC[m2][0][1]);
                    *(float2*)&pw[r1*16 + 2*tg] =
                        make_float2(accM[m2][0][2] + accC[m2][0][2],
                                    accM[m2][0][3] + accC[m2][0][3]);
                    *(float2*)&pw[r0*16 + 8 + 2*tg] =
                        make_float2(accM[m2][1][0] + accC[m2][1][0],
                                    accM[m2][1][1] + accC[m2][1][1]);
                    *(float2*)&pw[r1*16 + 8 + 2*tg] =
                        make_float2(accM[m2][1][2] + accC[m2][1][2],
                                    accM[m2][1][3] + accC[m2][1][3]);
                }
            }
            __syncthreads();

#pragma unroll
            for (int j = 0; j < 2; j++) {
                int idx = tid + 256*j;
                float s = base_r[j];
#pragma unroll
                for (int w = 0; w < 8; w++) s += part[w*512 + idx];
                int gt = idx >> 7;
                act_s[idx] = (gt == 2) ? ftanh(s) : fsig(s);
            }
            __syncthreads();

            if (tid < 128) {
                float iv = act_s[tid];
                float fv = act_s[128 + tid];
                float gv = act_s[256 + tid];
                float ov = act_s[384 + tid];
                float c = fv*c_s[tid] + iv*gv;
                c_s[tid] = c;
                float h = ov*ftanh(c);
                __nv_bfloat16 hh = __float2bfloat16(h);
                __nv_bfloat16 hl = __float2bfloat16(h - __bfloat162float(hh));
                int u = u0 + (tid >> 4), b = tid & 15;
                g_h1hi[t & 3][b*Hz + u] = hh;
                g_h1lo[t & 3][b*Hz + u] = hl;
                hs1[((size_t)(b*Sz + t))*Hz + u] = h;
            }
            __syncthreads();
            if (tid == 0) arrive(ctr1);
        }
    }
}

// ------------------------------------------------------------------
extern "C" void kernel_launch(void* const* d_in, const int* in_sizes, int n_in,
                              void* d_out, int out_size)
{
    const int*   src   = (const int*)  d_in[0];
    const float* w_emb = (const float*)d_in[1];
    const float* b_emb = (const float*)d_in[2];
    const float* w_ih0 = (const float*)d_in[3];
    const float* w_hh0 = (const float*)d_in[4];
    const float* b_ih0 = (const float*)d_in[5];
    const float* b_hh0 = (const float*)d_in[6];
    const float* w_ih1 = (const float*)d_in[7];
    const float* w_hh1 = (const float*)d_in[8];
    const float* b_ih1 = (const float*)d_in[9];
    const float* b_hh1 = (const float*)d_in[10];
    const float* w1    = (const float*)d_in[11];
    const float* b1    = (const float*)d_in[12];
    const float* w2    = (const float*)d_in[13];
    const float* b2    = (const float*)d_in[14];
    float* out = (float*)d_out;

    float *emb, *xp, *hs1, *hid;
    cudaGetSymbolAddress((void**)&emb, g_emb);
    cudaGetSymbolAddress((void**)&xp,  g_xproj);
    cudaGetSymbolAddress((void**)&hs1, g_hs1);
    cudaGetSymbolAddress((void**)&hid, g_hid);

    const int DSMEM = 2*16*HP*2 + 131072;   // 66048 + 128K = 197120
    cudaFuncSetAttribute(lstm_fused, cudaFuncAttributeMaxDynamicSharedMemorySize,
                         DSMEM);

    const int M = Bz * Sz;  // 8192

    embed_kernel<<<(M*Hz + 255)/256, 256>>>(src, w_emb, b_emb);
    reset_kernel<<<1, 64>>>();

    gemm_tf32<<<dim3(Gz/128, M/128), 256>>>(emb, w_ih0, b_ih0, b_hh0, xp,
                                            M, Gz, Hz, 0);

    lstm_fused<<<96, 256, DSMEM>>>(xp, w_hh0, w_ih1, w_hh1, b_ih1, b_hh1, hs1);

    gemm_tf32<<<dim3(1, M/128), 256>>>(hs1, w1, b1, nullptr, hid,
                                       M, 128, Hz, 1);

    gemm_tf32<<<dim3((Vz + 127)/128, M/128), 256>>>(hid, w2, b2, nullptr, out,
                                                    M, Vz, 128, 0);
}

// round 10
// speedup vs baseline: 1.3295x; 1.3295x over previous
#include <cuda_runtime.h>
#include <cuda_bf16.h>
#include <math.h>

#define Bz 16
#define Sz 512
#define Hz 512
#define Vz 10000
#define Gz 2048
#define HP 1032

// ---- scratch (static device globals) ----
__device__ float g_emb [Bz*Sz*Hz];
__device__ float g_xproj[Bz*Sz*Gz];
__device__ float g_hs1 [Bz*Sz*Hz];
__device__ float g_hid [Bz*Sz*128];
__device__ __align__(16) __nv_bfloat16 g_h0hi[4][Bz*Hz];
__device__ __align__(16) __nv_bfloat16 g_h0lo[4][Bz*Hz];
__device__ __align__(16) __nv_bfloat16 g_h1hi[4][Bz*Hz];
__device__ __align__(16) __nv_bfloat16 g_h1lo[4][Bz*Hz];
__device__ unsigned g_sync[64];   // ctr0 @0, ctr1 @32 (separate lines)

// ------------------------------------------------------------------
__global__ void reset_kernel() {
    if (threadIdx.x < 64) g_sync[threadIdx.x] = 0u;
}

__global__ void embed_kernel(const int* __restrict__ src,
                             const float* __restrict__ w_emb,
                             const float* __restrict__ b_emb)
{
    int idx = blockIdx.x * 256 + threadIdx.x;
    if (idx >= Bz*Sz*Hz) return;
    int h  = idx & (Hz-1);
    int bs = idx >> 9;
    int v  = src[bs];
    g_emb[idx] = w_emb[h*Vz + v] + b_emb[h];
}

// ------------------------------------------------------------------
// tf32 tensor-core GEMM (proven R4, unchanged).
__device__ __forceinline__ unsigned f2tf(float f) {
    unsigned u;
    asm("cvt.rna.tf32.f32 %0, %1;" : "=r"(u) : "f"(f));
    return u;
}
__device__ __forceinline__ void mma_tf32(float* d, const unsigned* a,
                                         const unsigned* b) {
    asm("mma.sync.aligned.m16n8k8.row.col.f32.tf32.tf32.f32 "
        "{%0,%1,%2,%3}, {%4,%5,%6,%7}, {%8,%9}, {%0,%1,%2,%3};"
        : "+f"(d[0]), "+f"(d[1]), "+f"(d[2]), "+f"(d[3])
        : "r"(a[0]), "r"(a[1]), "r"(a[2]), "r"(a[3]),
          "r"(b[0]), "r"(b[1]));
}

__global__ void __launch_bounds__(256)
gemm_tf32(const float* __restrict__ A, const float* __restrict__ B,
          const float* __restrict__ bias, const float* __restrict__ bias2,
          float* __restrict__ C, int M, int N, int K, int relu)
{
    __shared__ unsigned As[8*4*4*32];
    __shared__ unsigned Bs[16*4*2*32];

    const int tid = threadIdx.x;
    const int n0 = blockIdx.x * 128;
    const int m0 = blockIdx.y * 128;

    const int lm = tid >> 1;
    const int lk = (tid & 1) * 16;
    const float* Ap = A + (size_t)(m0 + lm) * K + lk;
    const float* Bp = B + (size_t)(n0 + lm) * K + lk;
    const bool bval = (n0 + lm) < N;

    const int warp = tid >> 5;
    const int lane = tid & 31;
    const int wm = warp >> 2;
    const int wn = warp & 3;

    float acc[4][4][4];
#pragma unroll
    for (int i = 0; i < 4; i++)
#pragma unroll
        for (int j = 0; j < 4; j++)
#pragma unroll
            for (int r = 0; r < 4; r++) acc[i][j][r] = 0.f;

    float4 a_r[4], b_r[4];
    const float4 z4 = make_float4(0.f, 0.f, 0.f, 0.f);
#pragma unroll
    for (int j = 0; j < 4; j++) {
        a_r[j] = *(const float4*)(Ap + 4*j);
        b_r[j] = bval ? *(const float4*)(Bp + 4*j) : z4;
    }

    const int mt_s = lm >> 4, r_s = lm & 15;
    const int nt_s = lm >> 3, ln_s = lm & 7;
    const int nch = K >> 5;

    for (int ch = 0; ch < nch; ch++) {
        __syncthreads();
#pragma unroll
        for (int j = 0; j < 4; j++) {
            int kc = lk + 4*j;
            int ks = kc >> 3;
            int cr = (kc & 7) >> 2;
            uint4 av = make_uint4(f2tf(a_r[j].x), f2tf(a_r[j].y),
                                  f2tf(a_r[j].z), f2tf(a_r[j].w));
            *(uint4*)&As[(((mt_s*4 + ks)*4) + cr*2 + (r_s >> 3))*32 + (r_s & 7)*4] = av;
            uint4 bv = make_uint4(f2tf(b_r[j].x), f2tf(b_r[j].y),
                                  f2tf(b_r[j].z), f2tf(b_r[j].w));
            *(uint4*)&Bs[(((nt_s*4 + ks)*2) + cr)*32 + ln_s*4] = bv;
        }
        __syncthreads();

        if (ch + 1 < nch) {
            const float* ap = Ap + (ch + 1)*32;
            const float* bp = Bp + (ch + 1)*32;
#pragma unroll
            for (int j = 0; j < 4; j++) {
                a_r[j] = *(const float4*)(ap + 4*j);
                b_r[j] = bval ? *(const float4*)(bp + 4*j) : z4;
            }
        }

#pragma unroll
        for (int ks = 0; ks < 4; ks++) {
            unsigned af[4][4];
#pragma unroll
            for (int mi = 0; mi < 4; mi++) {
                int base = (((wm*4 + mi)*4 + ks)*4)*32 + lane;
                af[mi][0] = As[base];
                af[mi][1] = As[base + 32];
                af[mi][2] = As[base + 64];
                af[mi][3] = As[base + 96];
            }
#pragma unroll
            for (int ni = 0; ni < 4; ni++) {
                int bb = (((wn*4 + ni)*4 + ks)*2)*32 + lane;
                unsigned bf[2] = { Bs[bb], Bs[bb + 32] };
#pragma unroll
                for (int mi = 0; mi < 4; mi++)
                    mma_tf32(acc[mi][ni], af[mi], bf);
            }
        }
    }

    const int g  = lane >> 2;
    const int tg = lane & 3;
#pragma unroll
    for (int ni = 0; ni < 4; ni++) {
        int ncol = n0 + wn*32 + ni*8 + tg*2;
        if (ncol < N) {
            float bb0 = bias[ncol]   + (bias2 ? bias2[ncol]   : 0.f);
            float bb1 = bias[ncol+1] + (bias2 ? bias2[ncol+1] : 0.f);
#pragma unroll
            for (int mi = 0; mi < 4; mi++) {
                int mrow = m0 + wm*64 + mi*16 + g;
                float2 v0 = make_float2(acc[mi][ni][0] + bb0,
                                        acc[mi][ni][1] + bb1);
                float2 v1 = make_float2(acc[mi][ni][2] + bb0,
                                        acc[mi][ni][3] + bb1);
                if (relu) {
                    v0.x = fmaxf(v0.x, 0.f); v0.y = fmaxf(v0.y, 0.f);
                    v1.x = fmaxf(v1.x, 0.f); v1.y = fmaxf(v1.y, 0.f);
                }
                *(float2*)(C + (size_t)mrow * N + ncol)       = v0;
                *(float2*)(C + (size_t)(mrow + 8) * N + ncol) = v1;
            }
        }
    }
}

// ------------------------------------------------------------------
__device__ __forceinline__ void poll_ge(unsigned* p, unsigned tgt) {
    unsigned v;
    do {
        asm volatile("ld.acquire.gpu.global.u32 %0, [%1];"
                     : "=r"(v) : "l"(p) : "memory");
    } while (v < tgt);
}
__device__ __forceinline__ void arrive(unsigned* p) {
    asm volatile("red.release.gpu.global.add.u32 [%0], 1;"
                 :: "l"(p) : "memory");
}

__device__ __forceinline__ unsigned pack_bf2(__nv_bfloat16 a, __nv_bfloat16 b) {
    return ((unsigned)__bfloat16_as_ushort(b) << 16) | __bfloat16_as_ushort(a);
}
__device__ __forceinline__ void mma_bf16(float* d, const unsigned* a,
                                         unsigned b0, unsigned b1) {
    asm("mma.sync.aligned.m16n8k16.row.col.f32.bf16.bf16.f32 "
        "{%0,%1,%2,%3}, {%4,%5,%6,%7}, {%8,%9}, {%0,%1,%2,%3};"
        : "+f"(d[0]), "+f"(d[1]), "+f"(d[2]), "+f"(d[3])
        : "r"(a[0]), "r"(a[1]), "r"(a[2]), "r"(a[3]), "r"(b0), "r"(b1));
}
__device__ __forceinline__ void ldsm_x4(unsigned& r0, unsigned& r1,
                                        unsigned& r2, unsigned& r3,
                                        unsigned addr) {
    asm volatile("ldmatrix.sync.aligned.m8n8.x4.shared.b16 {%0,%1,%2,%3}, [%4];"
                 : "=r"(r0), "=r"(r1), "=r"(r2), "=r"(r3) : "r"(addr));
}
__device__ __forceinline__ unsigned smem_u32(const void* p) {
    return (unsigned)__cvta_generic_to_shared(p);
}
__device__ __forceinline__ float fsig(float x) {
    return __fdividef(1.f, 1.f + __expf(-x));
}
__device__ __forceinline__ float ftanh(float x) {
    float xc = fminf(fmaxf(x, -15.f), 15.f);
    float e = __expf(2.f * xc);
    return __fdividef(e - 1.f, e + 1.f);
}

// ------------------------------------------------------------------
// Fused 2-layer wavefront LSTM (R8 structure). 96 CTAs: 32 L0 (16 units),
// 64 L1 (8 units, k=1024 concat). Decoupled counters, 4-deep h buffers,
// reg-resident A fragments (compile-time-bound loops!), ldmatrix B,
// fast activations, two-phase L1 staging.
__global__ void __launch_bounds__(256)
lstm_fused(const float* __restrict__ xproj,
           const float* __restrict__ w_hh0,
           const float* __restrict__ w_ih1,
           const float* __restrict__ w_hh1,
           const float* __restrict__ b_ih1,
           const float* __restrict__ b_hh1,
           float* __restrict__ hs1)
{
    extern __shared__ __align__(16) unsigned char dyn[];
    float* w_stage = (float*)dyn;                          // 128KB (init only)
    __nv_bfloat16* Hhi_s = (__nv_bfloat16*)(dyn + 131072); // [16][HP]
    __nv_bfloat16* Hlo_s = Hhi_s + 16*HP;
    float* part  = (float*)(Hlo_s + 16*HP);                // [2048]
    float* act_s = part + 2048;                            // [1024]
    float* c_s   = act_s + 1024;                           // [256]

    const int tid  = threadIdx.x;
    const int bid  = blockIdx.x;
    const bool is0 = bid < 32;
    const int u0   = is0 ? bid*16 : (bid-32)*8;
    const int warp = tid >> 5;
    const int lane = tid & 31;
    const int g    = lane >> 2;
    const int tg   = lane & 3;
    unsigned* ctr0 = g_sync;
    unsigned* ctr1 = g_sync + 32;

    const int Kw = is0 ? 512 : 1024;

    // ---- stage weights coalesced into SMEM ----
    for (int idx4 = tid; idx4 < 8192; idx4 += 256) {
        int row, k;
        if (is0) { row = idx4 >> 7; k = (idx4 & 127) * 4; }
        else     { row = idx4 >> 8; k = (idx4 & 255) * 4; }
        const float* W;
        int gate, koff;
        if (is0) {
            gate = (row >> 4)*Hz + u0 + (row & 15);
            W = w_hh0; koff = k;
        } else {
            gate = (row >> 3)*Hz + u0 + (row & 7);
            if (k < Hz) { W = w_ih1; koff = k; }
            else        { W = w_hh1; koff = k - Hz; }
        }
        *(float4*)(w_stage + row*Kw + k) =
            *(const float4*)(W + (size_t)gate*Hz + koff);
    }
    __syncthreads();

    // ---- A fragments -> registers (split-bf16); COMPILE-TIME bounds ----
    const int mt = is0 ? (warp & 3) : (warp & 1);
    const int kg = is0 ? (warp >> 2) : (warp >> 1);
    unsigned Ahi[16][4], Alo[16][4];
#pragma unroll
    for (int kk = 0; kk < 16; kk++) {
        int ks = kg*16 + kk;
#pragma unroll
        for (int r = 0; r < 4; r++) {
            int row = mt*16 + g + (r & 1)*8;
            int k   = ks*16 + 2*tg + (r >> 1)*8;
            float w0 = w_stage[row*Kw + k];
            float w1 = w_stage[row*Kw + k + 1];
            __nv_bfloat16 h0 = __float2bfloat16(w0);
            __nv_bfloat16 h1 = __float2bfloat16(w1);
            __nv_bfloat16 l0 = __float2bfloat16(w0 - __bfloat162float(h0));
            __nv_bfloat16 l1 = __float2bfloat16(w1 - __bfloat162float(h1));
            Ahi[kk][r] = pack_bf2(h0, h1);
            Alo[kk][r] = pack_bf2(l0, l1);
        }
    }

    // ---- ldmatrix lane addressing (B frags) ----
    const int mrow = lane >> 3, rr = lane & 7;
    const int nn   = ((mrow >> 1) << 3) + rr;
    const int kof  = (mrow & 1) * 8;
    const unsigned bhi_base = smem_u32(Hhi_s) + (nn*HP + kof)*2;
    const unsigned blo_base = bhi_base + 16*HP*2;

    // ---- init state + base (xproj / bias) ----
    float base_r[4];
    const __nv_bfloat16 zb = __float2bfloat16(0.f);
    if (is0) {
        c_s[tid] = 0.f;
        int u = u0 + (tid >> 4), b = tid & 15;
        g_h0hi[3][b*Hz + u] = zb;
        g_h0lo[3][b*Hz + u] = zb;
#pragma unroll
        for (int j = 0; j < 4; j++) {
            int idx = tid + 256*j;
            int lg = idx >> 4, b2 = idx & 15;
            int gate = (lg >> 4)*Hz + u0 + (lg & 15);
            base_r[j] = xproj[((size_t)(b2 << 9))*Gz + gate];
        }
    } else {
        if (tid < 128) {
            c_s[tid] = 0.f;
            int u = u0 + (tid >> 4), b = tid & 15;
            g_h1hi[3][b*Hz + u] = zb;
            g_h1lo[3][b*Hz + u] = zb;
        }
#pragma unroll
        for (int j = 0; j < 2; j++) {
            int idx = tid + 256*j;
            int lg = idx >> 4;
            int gate = (lg >> 3)*Hz + u0 + (lg & 7);
            base_r[j] = b_ih1[gate] + b_hh1[gate];
        }
    }
    __syncthreads();
    if (tid == 0) arrive(is0 ? ctr0 : ctr1);

    if (is0) {
        // ============ LAYER 0: rounds r = 0..511 ============
        for (int r = 0; r < Sz; r++) {
            if (tid < 2) {
                unsigned* p  = (tid == 0) ? ctr0 : ctr1;
                unsigned tgt = (tid == 0) ? 32u*(r+1)
                             : (r >= 3 ? 64u*(r-2) : 0u);
                if (tgt) poll_ge(p, tgt);
            }
            __syncthreads();

            {   // stage h0_{r-1} (slot (r+3)&3)
                const uint4* ghi = (const uint4*)g_h0hi[(r+3)&3];
                const uint4* glo = (const uint4*)g_h0lo[(r+3)&3];
#pragma unroll
                for (int i = 0; i < 4; i++) {
                    int idx = tid + 256*i;
                    int b = idx >> 6, uo = (idx & 63)*8;
                    uint4 vh = __ldcg(ghi + idx);
                    uint4 vl = __ldcg(glo + idx);
                    *(uint4*)(Hhi_s + b*HP + uo) = vh;
                    *(uint4*)(Hlo_s + b*HP + uo) = vl;
                }
            }
            float nxt[4];
            {
                int tn = (r + 1 < Sz) ? r + 1 : r;
#pragma unroll
                for (int j = 0; j < 4; j++) {
                    int idx = tid + 256*j;
                    int lg = idx >> 4, b2 = idx & 15;
                    int gate = (lg >> 4)*Hz + u0 + (lg & 15);
                    nxt[j] = xproj[((size_t)((b2 << 9) | tn))*Gz + gate];
                }
            }
            __syncthreads();

            float aA0[4]={0,0,0,0}, aB0[4]={0,0,0,0}, aC0[4]={0,0,0,0};
            float aA1[4]={0,0,0,0}, aB1[4]={0,0,0,0}, aC1[4]={0,0,0,0};
#pragma unroll
            for (int kk = 0; kk < 16; kk++) {
                int ks = kg*16 + kk;
                unsigned bh0,bh1,bh2,bh3, bl0,bl1,bl2,bl3;
                ldsm_x4(bh0,bh1,bh2,bh3, bhi_base + ks*32);
                ldsm_x4(bl0,bl1,bl2,bl3, blo_base + ks*32);
                mma_bf16(aA0, Ahi[kk], bh0, bh1);
                mma_bf16(aA1, Ahi[kk], bh2, bh3);
                mma_bf16(aB0, Ahi[kk], bl0, bl1);
                mma_bf16(aB1, Ahi[kk], bl2, bl3);
                mma_bf16(aC0, Alo[kk], bh0, bh1);
                mma_bf16(aC1, Alo[kk], bh2, bh3);
            }
            float acc0[4], acc1[4];
#pragma unroll
            for (int q = 0; q < 4; q++) {
                acc0[q] = aA0[q] + aB0[q] + aC0[q];
                acc1[q] = aA1[q] + aB1[q] + aC1[q];
            }
            float* pw = part + kg*1024;
            *(float2*)&pw[(mt*16 + g)*16 + 2*tg]         = make_float2(acc0[0], acc0[1]);
            *(float2*)&pw[(mt*16 + g + 8)*16 + 2*tg]     = make_float2(acc0[2], acc0[3]);
            *(float2*)&pw[(mt*16 + g)*16 + 8 + 2*tg]     = make_float2(acc1[0], acc1[1]);
            *(float2*)&pw[(mt*16 + g + 8)*16 + 8 + 2*tg] = make_float2(acc1[2], acc1[3]);
            __syncthreads();

#pragma unroll
            for (int j = 0; j < 4; j++) {
                int idx = tid + 256*j;
                float s = base_r[j] + part[idx] + part[1024 + idx];
                int gt = idx >> 8;
                act_s[idx] = (gt == 2) ? ftanh(s) : fsig(s);
            }
            __syncthreads();

            {
                float iv = act_s[tid];
                float fv = act_s[256 + tid];
                float gv = act_s[512 + tid];
                float ov = act_s[768 + tid];
                float c = fv*c_s[tid] + iv*gv;
                c_s[tid] = c;
                float h = ov*ftanh(c);
                __nv_bfloat16 hh = __float2bfloat16(h);
                __nv_bfloat16 hl = __float2bfloat16(h - __bfloat162float(hh));
                int u = u0 + (tid >> 4), b = tid & 15;
                g_h0hi[r & 3][b*Hz + u] = hh;
                g_h0lo[r & 3][b*Hz + u] = hl;
            }
#pragma unroll
            for (int j = 0; j < 4; j++) base_r[j] = nxt[j];
            __syncthreads();
            if (tid == 0) arrive(ctr0);
        }
    } else {
        // ============ LAYER 1: rounds r = 1..512 ============
        for (int r = 1; r <= Sz; r++) {
            const int t = r - 1;
            // phase 1: own h1_{t-1} is ready after our previous arrive;
            // wait only on ctr1 then stage it (hides under L0's lead)
            if (tid == 0) poll_ge(ctr1, 64u*r);
            __syncthreads();
            {
                const uint4* g1h = (const uint4*)g_h1hi[(t+3) & 3];
                const uint4* g1l = (const uint4*)g_h1lo[(t+3) & 3];
#pragma unroll
                for (int i = 0; i < 4; i++) {
                    int idx = tid + 256*i;
                    int b = idx >> 6, uo = (idx & 63)*8;
                    uint4 wh = __ldcg(g1h + idx);
                    uint4 wl = __ldcg(g1l + idx);
                    *(uint4*)(Hhi_s + b*HP + 512 + uo) = wh;
                    *(uint4*)(Hlo_s + b*HP + 512 + uo) = wl;
                }
            }
            // phase 2: wait for L0's h0_t, then stage it
            if (tid == 0) poll_ge(ctr0, 32u*(r+1));
            __syncthreads();
            {
                const uint4* g0h = (const uint4*)g_h0hi[t & 3];
                const uint4* g0l = (const uint4*)g_h0lo[t & 3];
#pragma unroll
                for (int i = 0; i < 4; i++) {
                    int idx = tid + 256*i;
                    int b = idx >> 6, uo = (idx & 63)*8;
                    uint4 vh = __ldcg(g0h + idx);
                    uint4 vl = __ldcg(g0l + idx);
                    *(uint4*)(Hhi_s + b*HP + uo) = vh;
                    *(uint4*)(Hlo_s + b*HP + uo) = vl;
                }
            }
            __syncthreads();

            float aA0[4]={0,0,0,0}, aB0[4]={0,0,0,0}, aC0[4]={0,0,0,0};
            float aA1[4]={0,0,0,0}, aB1[4]={0,0,0,0}, aC1[4]={0,0,0,0};
#pragma unroll
            for (int kk = 0; kk < 16; kk++) {
                int ks = kg*16 + kk;
                unsigned bh0,bh1,bh2,bh3, bl0,bl1,bl2,bl3;
                ldsm_x4(bh0,bh1,bh2,bh3, bhi_base + ks*32);
                ldsm_x4(bl0,bl1,bl2,bl3, blo_base + ks*32);
                mma_bf16(aA0, Ahi[kk], bh0, bh1);
                mma_bf16(aA1, Ahi[kk], bh2, bh3);
                mma_bf16(aB0, Ahi[kk], bl0, bl1);
                mma_bf16(aB1, Ahi[kk], bl2, bl3);
                mma_bf16(aC0, Alo[kk], bh0, bh1);
                mma_bf16(aC1, Alo[kk], bh2, bh3);
            }
            float acc0[4], acc1[4];
#pragma unroll
            for (int q = 0; q < 4; q++) {
                acc0[q] = aA0[q] + aB0[q] + aC0[q];
                acc1[q] = aA1[q] + aB1[q] + aC1[q];
            }
            float* pw = part + kg*512;
            *(float2*)&pw[(mt*16 + g)*16 + 2*tg]         = make_float2(acc0[0], acc0[1]);
            *(float2*)&pw[(mt*16 + g + 8)*16 + 2*tg]     = make_float2(acc0[2], acc0[3]);
            *(float2*)&pw[(mt*16 + g)*16 + 8 + 2*tg]     = make_float2(acc1[0], acc1[1]);
            *(float2*)&pw[(mt*16 + g + 8)*16 + 8 + 2*tg] = make_float2(acc1[2], acc1[3]);
            __syncthreads();

#pragma unroll
            for (int j = 0; j < 2; j++) {
                int idx = tid + 256*j;
                if (idx < 512) {
                    float s = base_r[j] + part[idx] + part[512 + idx]
                            + part[1024 + idx] + part[1536 + idx];
                    int gt = idx >> 7;
                    act_s[idx] = (gt == 2) ? ftanh(s) : fsig(s);
                }
            }
            __syncthreads();

            if (tid < 128) {
                float iv = act_s[tid];
                float fv = act_s[128 + tid];
                float gv = act_s[256 + tid];
                float ov = act_s[384 + tid];
                float c = fv*c_s[tid] + iv*gv;
                c_s[tid] = c;
                float h = ov*ftanh(c);
                __nv_bfloat16 hh = __float2bfloat16(h);
                __nv_bfloat16 hl = __float2bfloat16(h - __bfloat162float(hh));
                int u = u0 + (tid >> 4), b = tid & 15;
                g_h1hi[t & 3][b*Hz + u] = hh;
                g_h1lo[t & 3][b*Hz + u] = hl;
                hs1[((size_t)(b*Sz + t))*Hz + u] = h;
            }
            __syncthreads();
            if (tid == 0) arrive(ctr1);
        }
    }
}

// ------------------------------------------------------------------
extern "C" void kernel_launch(void* const* d_in, const int* in_sizes, int n_in,
                              void* d_out, int out_size)
{
    const int*   src   = (const int*)  d_in[0];
    const float* w_emb = (const float*)d_in[1];
    const float* b_emb = (const float*)d_in[2];
    const float* w_ih0 = (const float*)d_in[3];
    const float* w_hh0 = (const float*)d_in[4];
    const float* b_ih0 = (const float*)d_in[5];
    const float* b_hh0 = (const float*)d_in[6];
    const float* w_ih1 = (const float*)d_in[7];
    const float* w_hh1 = (const float*)d_in[8];
    const float* b_ih1 = (const float*)d_in[9];
    const float* b_hh1 = (const float*)d_in[10];
    const float* w1    = (const float*)d_in[11];
    const float* b1    = (const float*)d_in[12];
    const float* w2    = (const float*)d_in[13];
    const float* b2    = (const float*)d_in[14];
    float* out = (float*)d_out;

    float *emb, *xp, *hs1, *hid;
    cudaGetSymbolAddress((void**)&emb, g_emb);
    cudaGetSymbolAddress((void**)&xp,  g_xproj);
    cudaGetSymbolAddress((void**)&hs1, g_hs1);
    cudaGetSymbolAddress((void**)&hid, g_hid);

    const int DSMEM = 131072 + 2*16*HP*2 + (2048 + 1024 + 256)*4;
    cudaFuncSetAttribute(lstm_fused, cudaFuncAttributeMaxDynamicSharedMemorySize,
                         DSMEM);

    const int M = Bz * Sz;  // 8192

    embed_kernel<<<(M*Hz + 255)/256, 256>>>(src, w_emb, b_emb);
    reset_kernel<<<1, 64>>>();

    gemm_tf32<<<dim3(Gz/128, M/128), 256>>>(emb, w_ih0, b_ih0, b_hh0, xp,
                                            M, Gz, Hz, 0);

    lstm_fused<<<96, 256, DSMEM>>>(xp, w_hh0, w_ih1, w_hh1, b_ih1, b_hh1, hs1);

    gemm_tf32<<<dim3(1, M/128), 256>>>(hs1, w1, b1, nullptr, hid,
                                       M, 128, Hz, 1);

    gemm_tf32<<<dim3((Vz + 127)/128, M/128), 256>>>(hid, w2, b2, nullptr, out,
                                                    M, Vz, 128, 0);
}

// round 11
// speedup vs baseline: 1.4588x; 1.0973x over previous
#include <cuda_runtime.h>
#include <cuda_bf16.h>
#include <math.h>

#define Bz 16
#define Sz 512
#define Hz 512
#define Vz 10000
#define Gz 2048
#define HP 1032

// ---- scratch (static device globals) ----
__device__ float g_emb [Bz*Sz*Hz];
__device__ float g_xproj[Bz*Sz*Gz];
__device__ float g_hs1 [Bz*Sz*Hz];
__device__ float g_hid [Bz*Sz*128];
__device__ __align__(16) __nv_bfloat16 g_h0hi[4][Bz*Hz];
__device__ __align__(16) __nv_bfloat16 g_h0lo[4][Bz*Hz];
__device__ __align__(16) __nv_bfloat16 g_h1hi[4][Bz*Hz];
__device__ __align__(16) __nv_bfloat16 g_h1lo[4][Bz*Hz];
__device__ unsigned g_sync[64];   // ctr0 @0, ctr1 @32 (separate lines)

// ------------------------------------------------------------------
__global__ void reset_kernel() {
    if (threadIdx.x < 64) g_sync[threadIdx.x] = 0u;
}

__global__ void embed_kernel(const int* __restrict__ src,
                             const float* __restrict__ w_emb,
                             const float* __restrict__ b_emb)
{
    int idx = blockIdx.x * 256 + threadIdx.x;
    if (idx >= Bz*Sz*Hz) return;
    int h  = idx & (Hz-1);
    int bs = idx >> 9;
    int v  = src[bs];
    g_emb[idx] = w_emb[h*Vz + v] + b_emb[h];
}

// ------------------------------------------------------------------
// tf32 tensor-core GEMM (proven R4, unchanged).
__device__ __forceinline__ unsigned f2tf(float f) {
    unsigned u;
    asm("cvt.rna.tf32.f32 %0, %1;" : "=r"(u) : "f"(f));
    return u;
}
__device__ __forceinline__ void mma_tf32(float* d, const unsigned* a,
                                         const unsigned* b) {
    asm("mma.sync.aligned.m16n8k8.row.col.f32.tf32.tf32.f32 "
        "{%0,%1,%2,%3}, {%4,%5,%6,%7}, {%8,%9}, {%0,%1,%2,%3};"
        : "+f"(d[0]), "+f"(d[1]), "+f"(d[2]), "+f"(d[3])
        : "r"(a[0]), "r"(a[1]), "r"(a[2]), "r"(a[3]),
          "r"(b[0]), "r"(b[1]));
}

__global__ void __launch_bounds__(256)
gemm_tf32(const float* __restrict__ A, const float* __restrict__ B,
          const float* __restrict__ bias, const float* __restrict__ bias2,
          float* __restrict__ C, int M, int N, int K, int relu)
{
    __shared__ unsigned As[8*4*4*32];
    __shared__ unsigned Bs[16*4*2*32];

    const int tid = threadIdx.x;
    const int n0 = blockIdx.x * 128;
    const int m0 = blockIdx.y * 128;

    const int lm = tid >> 1;
    const int lk = (tid & 1) * 16;
    const float* Ap = A + (size_t)(m0 + lm) * K + lk;
    const float* Bp = B + (size_t)(n0 + lm) * K + lk;
    const bool bval = (n0 + lm) < N;

    const int warp = tid >> 5;
    const int lane = tid & 31;
    const int wm = warp >> 2;
    const int wn = warp & 3;

    float acc[4][4][4];
#pragma unroll
    for (int i = 0; i < 4; i++)
#pragma unroll
        for (int j = 0; j < 4; j++)
#pragma unroll
            for (int r = 0; r < 4; r++) acc[i][j][r] = 0.f;

    float4 a_r[4], b_r[4];
    const float4 z4 = make_float4(0.f, 0.f, 0.f, 0.f);
#pragma unroll
    for (int j = 0; j < 4; j++) {
        a_r[j] = *(const float4*)(Ap + 4*j);
        b_r[j] = bval ? *(const float4*)(Bp + 4*j) : z4;
    }

    const int mt_s = lm >> 4, r_s = lm & 15;
    const int nt_s = lm >> 3, ln_s = lm & 7;
    const int nch = K >> 5;

    for (int ch = 0; ch < nch; ch++) {
        __syncthreads();
#pragma unroll
        for (int j = 0; j < 4; j++) {
            int kc = lk + 4*j;
            int ks = kc >> 3;
            int cr = (kc & 7) >> 2;
            uint4 av = make_uint4(f2tf(a_r[j].x), f2tf(a_r[j].y),
                                  f2tf(a_r[j].z), f2tf(a_r[j].w));
            *(uint4*)&As[(((mt_s*4 + ks)*4) + cr*2 + (r_s >> 3))*32 + (r_s & 7)*4] = av;
            uint4 bv = make_uint4(f2tf(b_r[j].x), f2tf(b_r[j].y),
                                  f2tf(b_r[j].z), f2tf(b_r[j].w));
            *(uint4*)&Bs[(((nt_s*4 + ks)*2) + cr)*32 + ln_s*4] = bv;
        }
        __syncthreads();

        if (ch + 1 < nch) {
            const float* ap = Ap + (ch + 1)*32;
            const float* bp = Bp + (ch + 1)*32;
#pragma unroll
            for (int j = 0; j < 4; j++) {
                a_r[j] = *(const float4*)(ap + 4*j);
                b_r[j] = bval ? *(const float4*)(bp + 4*j) : z4;
            }
        }

#pragma unroll
        for (int ks = 0; ks < 4; ks++) {
            unsigned af[4][4];
#pragma unroll
            for (int mi = 0; mi < 4; mi++) {
                int base = (((wm*4 + mi)*4 + ks)*4)*32 + lane;
                af[mi][0] = As[base];
                af[mi][1] = As[base + 32];
                af[mi][2] = As[base + 64];
                af[mi][3] = As[base + 96];
            }
#pragma unroll
            for (int ni = 0; ni < 4; ni++) {
                int bb = (((wn*4 + ni)*4 + ks)*2)*32 + lane;
                unsigned bf[2] = { Bs[bb], Bs[bb + 32] };
#pragma unroll
                for (int mi = 0; mi < 4; mi++)
                    mma_tf32(acc[mi][ni], af[mi], bf);
            }
        }
    }

    const int g  = lane >> 2;
    const int tg = lane & 3;
#pragma unroll
    for (int ni = 0; ni < 4; ni++) {
        int ncol = n0 + wn*32 + ni*8 + tg*2;
        if (ncol < N) {
            float bb0 = bias[ncol]   + (bias2 ? bias2[ncol]   : 0.f);
            float bb1 = bias[ncol+1] + (bias2 ? bias2[ncol+1] : 0.f);
#pragma unroll
            for (int mi = 0; mi < 4; mi++) {
                int mrow = m0 + wm*64 + mi*16 + g;
                float2 v0 = make_float2(acc[mi][ni][0] + bb0,
                                        acc[mi][ni][1] + bb1);
                float2 v1 = make_float2(acc[mi][ni][2] + bb0,
                                        acc[mi][ni][3] + bb1);
                if (relu) {
                    v0.x = fmaxf(v0.x, 0.f); v0.y = fmaxf(v0.y, 0.f);
                    v1.x = fmaxf(v1.x, 0.f); v1.y = fmaxf(v1.y, 0.f);
                }
                *(float2*)(C + (size_t)mrow * N + ncol)       = v0;
                *(float2*)(C + (size_t)(mrow + 8) * N + ncol) = v1;
            }
        }
    }
}

// ------------------------------------------------------------------
__device__ __forceinline__ void poll_ge(unsigned* p, unsigned tgt) {
    unsigned v;
    do {
        asm volatile("ld.acquire.gpu.global.u32 %0, [%1];"
                     : "=r"(v) : "l"(p) : "memory");
    } while (v < tgt);
}
__device__ __forceinline__ void arrive(unsigned* p) {
    asm volatile("red.release.gpu.global.add.u32 [%0], 1;"
                 :: "l"(p) : "memory");
}

__device__ __forceinline__ unsigned pack_bf2(__nv_bfloat16 a, __nv_bfloat16 b) {
    return ((unsigned)__bfloat16_as_ushort(b) << 16) | __bfloat16_as_ushort(a);
}
__device__ __forceinline__ void mma_bf16(float* d, const unsigned* a,
                                         unsigned b0, unsigned b1) {
    asm("mma.sync.aligned.m16n8k16.row.col.f32.bf16.bf16.f32 "
        "{%0,%1,%2,%3}, {%4,%5,%6,%7}, {%8,%9}, {%0,%1,%2,%3};"
        : "+f"(d[0]), "+f"(d[1]), "+f"(d[2]), "+f"(d[3])
        : "r"(a[0]), "r"(a[1]), "r"(a[2]), "r"(a[3]), "r"(b0), "r"(b1));
}
__device__ __forceinline__ void ldsm_x4(unsigned& r0, unsigned& r1,
                                        unsigned& r2, unsigned& r3,
                                        unsigned addr) {
    asm volatile("ldmatrix.sync.aligned.m8n8.x4.shared.b16 {%0,%1,%2,%3}, [%4];"
                 : "=r"(r0), "=r"(r1), "=r"(r2), "=r"(r3) : "r"(addr));
}
__device__ __forceinline__ unsigned smem_u32(const void* p) {
    return (unsigned)__cvta_generic_to_shared(p);
}
__device__ __forceinline__ float fsig(float x) {
    return __fdividef(1.f, 1.f + __expf(-x));
}
__device__ __forceinline__ float ftanh(float x) {
    float xc = fminf(fmaxf(x, -15.f), 15.f);
    float e = __expf(2.f * xc);
    return __fdividef(e - 1.f, e + 1.f);
}

// ------------------------------------------------------------------
// Fused 2-layer wavefront LSTM — EXACT R8 structure (2288us proven),
// only change: fast activations. 96 CTAs: 32 L0 (16 units), 64 L1
// (8 units, k=1024 concat). Decoupled counters, 4-deep h buffers,
// reg-resident A fragments, ldmatrix B fragments.
__global__ void __launch_bounds__(256)
lstm_fused(const float* __restrict__ xproj,
           const float* __restrict__ w_hh0,
           const float* __restrict__ w_ih1,
           const float* __restrict__ w_hh1,
           const float* __restrict__ b_ih1,
           const float* __restrict__ b_hh1,
           float* __restrict__ hs1)
{
    extern __shared__ __align__(16) unsigned char dyn[];
    float* w_stage = (float*)dyn;                          // 128KB (init only)
    __nv_bfloat16* Hhi_s = (__nv_bfloat16*)(dyn + 131072); // [16][HP]
    __nv_bfloat16* Hlo_s = Hhi_s + 16*HP;
    float* part  = (float*)(Hlo_s + 16*HP);                // [2048]
    float* act_s = part + 2048;                            // [1024]
    float* c_s   = act_s + 1024;                           // [256]

    const int tid  = threadIdx.x;
    const int bid  = blockIdx.x;
    const bool is0 = bid < 32;
    const int u0   = is0 ? bid*16 : (bid-32)*8;
    const int warp = tid >> 5;
    const int lane = tid & 31;
    const int g    = lane >> 2;
    const int tg   = lane & 3;
    unsigned* ctr0 = g_sync;
    unsigned* ctr1 = g_sync + 32;

    const int Kw = is0 ? 512 : 1024;

    // ---- stage weights coalesced into SMEM ----
    for (int idx4 = tid; idx4 < 8192; idx4 += 256) {
        int row, k;
        if (is0) { row = idx4 >> 7; k = (idx4 & 127) * 4; }
        else     { row = idx4 >> 8; k = (idx4 & 255) * 4; }
        const float* W;
        int gate, koff;
        if (is0) {
            gate = (row >> 4)*Hz + u0 + (row & 15);
            W = w_hh0; koff = k;
        } else {
            gate = (row >> 3)*Hz + u0 + (row & 7);
            if (k < Hz) { W = w_ih1; koff = k; }
            else        { W = w_hh1; koff = k - Hz; }
        }
        *(float4*)(w_stage + row*Kw + k) =
            *(const float4*)(W + (size_t)gate*Hz + koff);
    }
    __syncthreads();

    // ---- A fragments -> registers (split-bf16); compile-time bounds ----
    const int mt = is0 ? (warp & 3) : (warp & 1);
    const int kg = is0 ? (warp >> 2) : (warp >> 1);
    unsigned Ahi[16][4], Alo[16][4];
#pragma unroll
    for (int kk = 0; kk < 16; kk++) {
        int ks = kg*16 + kk;
#pragma unroll
        for (int r = 0; r < 4; r++) {
            int row = mt*16 + g + (r & 1)*8;
            int k   = ks*16 + 2*tg + (r >> 1)*8;
            float w0 = w_stage[row*Kw + k];
            float w1 = w_stage[row*Kw + k + 1];
            __nv_bfloat16 h0 = __float2bfloat16(w0);
            __nv_bfloat16 h1 = __float2bfloat16(w1);
            __nv_bfloat16 l0 = __float2bfloat16(w0 - __bfloat162float(h0));
            __nv_bfloat16 l1 = __float2bfloat16(w1 - __bfloat162float(h1));
            Ahi[kk][r] = pack_bf2(h0, h1);
            Alo[kk][r] = pack_bf2(l0, l1);
        }
    }

    // ---- ldmatrix lane addressing (B frags) ----
    const int mrow = lane >> 3, rr = lane & 7;
    const int nn   = ((mrow >> 1) << 3) + rr;
    const int kof  = (mrow & 1) * 8;
    const unsigned bhi_base = smem_u32(Hhi_s) + (nn*HP + kof)*2;
    const unsigned blo_base = bhi_base + 16*HP*2;

    // ---- init state + base (xproj / bias) ----
    float base_r[4];
    const __nv_bfloat16 zb = __float2bfloat16(0.f);
    if (is0) {
        c_s[tid] = 0.f;
        int u = u0 + (tid >> 4), b = tid & 15;
        g_h0hi[3][b*Hz + u] = zb;
        g_h0lo[3][b*Hz + u] = zb;
#pragma unroll
        for (int j = 0; j < 4; j++) {
            int idx = tid + 256*j;
            int lg = idx >> 4, b2 = idx & 15;
            int gate = (lg >> 4)*Hz + u0 + (lg & 15);
            base_r[j] = xproj[((size_t)(b2 << 9))*Gz + gate];
        }
    } else {
        if (tid < 128) {
            c_s[tid] = 0.f;
            int u = u0 + (tid >> 4), b = tid & 15;
            g_h1hi[3][b*Hz + u] = zb;
            g_h1lo[3][b*Hz + u] = zb;
        }
#pragma unroll
        for (int j = 0; j < 2; j++) {
            int idx = tid + 256*j;
            int lg = idx >> 4;
            int gate = (lg >> 3)*Hz + u0 + (lg & 7);
            base_r[j] = b_ih1[gate] + b_hh1[gate];
        }
    }
    __syncthreads();
    if (tid == 0) arrive(is0 ? ctr0 : ctr1);

    if (is0) {
        // ============ LAYER 0: rounds r = 0..511 ============
        for (int r = 0; r < Sz; r++) {
            if (tid < 2) {
                unsigned* p  = (tid == 0) ? ctr0 : ctr1;
                unsigned tgt = (tid == 0) ? 32u*(r+1)
                             : (r >= 3 ? 64u*(r-2) : 0u);
                if (tgt) poll_ge(p, tgt);
            }
            __syncthreads();

            {   // stage h0_{r-1} (slot (r+3)&3)
                const uint4* ghi = (const uint4*)g_h0hi[(r+3)&3];
                const uint4* glo = (const uint4*)g_h0lo[(r+3)&3];
#pragma unroll
                for (int i = 0; i < 4; i++) {
                    int idx = tid + 256*i;
                    int b = idx >> 6, uo = (idx & 63)*8;
                    uint4 vh = __ldcg(ghi + idx);
                    uint4 vl = __ldcg(glo + idx);
                    *(uint4*)(Hhi_s + b*HP + uo) = vh;
                    *(uint4*)(Hlo_s + b*HP + uo) = vl;
                }
            }
            float nxt[4];
            {
                int tn = (r + 1 < Sz) ? r + 1 : r;
#pragma unroll
                for (int j = 0; j < 4; j++) {
                    int idx = tid + 256*j;
                    int lg = idx >> 4, b2 = idx & 15;
                    int gate = (lg >> 4)*Hz + u0 + (lg & 15);
                    nxt[j] = xproj[((size_t)((b2 << 9) | tn))*Gz + gate];
                }
            }
            __syncthreads();

            float aA0[4]={0,0,0,0}, aB0[4]={0,0,0,0}, aC0[4]={0,0,0,0};
            float aA1[4]={0,0,0,0}, aB1[4]={0,0,0,0}, aC1[4]={0,0,0,0};
#pragma unroll
            for (int kk = 0; kk < 16; kk++) {
                int ks = kg*16 + kk;
                unsigned bh0,bh1,bh2,bh3, bl0,bl1,bl2,bl3;
                ldsm_x4(bh0,bh1,bh2,bh3, bhi_base + ks*32);
                ldsm_x4(bl0,bl1,bl2,bl3, blo_base + ks*32);
                mma_bf16(aA0, Ahi[kk], bh0, bh1);
                mma_bf16(aA1, Ahi[kk], bh2, bh3);
                mma_bf16(aB0, Ahi[kk], bl0, bl1);
                mma_bf16(aB1, Ahi[kk], bl2, bl3);
                mma_bf16(aC0, Alo[kk], bh0, bh1);
                mma_bf16(aC1, Alo[kk], bh2, bh3);
            }
            float acc0[4], acc1[4];
#pragma unroll
            for (int q = 0; q < 4; q++) {
                acc0[q] = aA0[q] + aB0[q] + aC0[q];
                acc1[q] = aA1[q] + aB1[q] + aC1[q];
            }
            float* pw = part + kg*1024;
            *(float2*)&pw[(mt*16 + g)*16 + 2*tg]         = make_float2(acc0[0], acc0[1]);
            *(float2*)&pw[(mt*16 + g + 8)*16 + 2*tg]     = make_float2(acc0[2], acc0[3]);
            *(float2*)&pw[(mt*16 + g)*16 + 8 + 2*tg]     = make_float2(acc1[0], acc1[1]);
            *(float2*)&pw[(mt*16 + g + 8)*16 + 8 + 2*tg] = make_float2(acc1[2], acc1[3]);
            __syncthreads();

#pragma unroll
            for (int j = 0; j < 4; j++) {
                int idx = tid + 256*j;
                float s = base_r[j] + part[idx] + part[1024 + idx];
                int gt = idx >> 8;
                act_s[idx] = (gt == 2) ? ftanh(s) : fsig(s);
            }
            __syncthreads();

            {
                float iv = act_s[tid];
                float fv = act_s[256 + tid];
                float gv = act_s[512 + tid];
                float ov = act_s[768 + tid];
                float c = fv*c_s[tid] + iv*gv;
                c_s[tid] = c;
                float h = ov*ftanh(c);
                __nv_bfloat16 hh = __float2bfloat16(h);
                __nv_bfloat16 hl = __float2bfloat16(h - __bfloat162float(hh));
                int u = u0 + (tid >> 4), b = tid & 15;
                g_h0hi[r & 3][b*Hz + u] = hh;
                g_h0lo[r & 3][b*Hz + u] = hl;
            }
#pragma unroll
            for (int j = 0; j < 4; j++) base_r[j] = nxt[j];
            __syncthreads();
            if (tid == 0) arrive(ctr0);
        }
    } else {
        // ============ LAYER 1: rounds r = 1..512 ============
        for (int r = 1; r <= Sz; r++) {
            const int t = r - 1;
            if (tid < 2) {
                unsigned* p  = (tid == 0) ? ctr0 : ctr1;
                unsigned tgt = (tid == 0) ? 32u*(r+1) : 64u*r;
                poll_ge(p, tgt);
            }
            __syncthreads();

            // stage h0_t (slot t&3) -> cols [0,512); h1_{t-1} (slot (t+3)&3) -> [512,1024)
            {
                const uint4* g0h = (const uint4*)g_h0hi[t & 3];
                const uint4* g0l = (const uint4*)g_h0lo[t & 3];
                const uint4* g1h = (const uint4*)g_h1hi[(t+3) & 3];
                const uint4* g1l = (const uint4*)g_h1lo[(t+3) & 3];
#pragma unroll
                for (int i = 0; i < 4; i++) {
                    int idx = tid + 256*i;
                    int b = idx >> 6, uo = (idx & 63)*8;
                    uint4 vh = __ldcg(g0h + idx);
                    uint4 vl = __ldcg(g0l + idx);
                    *(uint4*)(Hhi_s + b*HP + uo) = vh;
                    *(uint4*)(Hlo_s + b*HP + uo) = vl;
                    uint4 wh = __ldcg(g1h + idx);
                    uint4 wl = __ldcg(g1l + idx);
                    *(uint4*)(Hhi_s + b*HP + 512 + uo) = wh;
                    *(uint4*)(Hlo_s + b*HP + 512 + uo) = wl;
                }
            }
            __syncthreads();

            float aA0[4]={0,0,0,0}, aB0[4]={0,0,0,0}, aC0[4]={0,0,0,0};
            float aA1[4]={0,0,0,0}, aB1[4]={0,0,0,0}, aC1[4]={0,0,0,0};
#pragma unroll
            for (int kk = 0; kk < 16; kk++) {
                int ks = kg*16 + kk;
                unsigned bh0,bh1,bh2,bh3, bl0,bl1,bl2,bl3;
                ldsm_x4(bh0,bh1,bh2,bh3, bhi_base + ks*32);
                ldsm_x4(bl0,bl1,bl2,bl3, blo_base + ks*32);
                mma_bf16(aA0, Ahi[kk], bh0, bh1);
                mma_bf16(aA1, Ahi[kk], bh2, bh3);
                mma_bf16(aB0, Ahi[kk], bl0, bl1);
                mma_bf16(aB1, Ahi[kk], bl2, bl3);
                mma_bf16(aC0, Alo[kk], bh0, bh1);
                mma_bf16(aC1, Alo[kk], bh2, bh3);
            }
            float acc0[4], acc1[4];
#pragma unroll
            for (int q = 0; q < 4; q++) {
                acc0[q] = aA0[q] + aB0[q] + aC0[q];
                acc1[q] = aA1[q] + aB1[q] + aC1[q];
            }
            float* pw = part + kg*512;
            *(float2*)&pw[(mt*16 + g)*16 + 2*tg]         = make_float2(acc0[0], acc0[1]);
            *(float2*)&pw[(mt*16 + g + 8)*16 + 2*tg]     = make_float2(acc0[2], acc0[3]);
            *(float2*)&pw[(mt*16 + g)*16 + 8 + 2*tg]     = make_float2(acc1[0], acc1[1]);
            *(float2*)&pw[(mt*16 + g + 8)*16 + 8 + 2*tg] = make_float2(acc1[2], acc1[3]);
            __syncthreads();

#pragma unroll
            for (int j = 0; j < 2; j++) {
                int idx = tid + 256*j;
                if (idx < 512) {
                    float s = base_r[j] + part[idx] + part[512 + idx]
                            + part[1024 + idx] + part[1536 + idx];
                    int gt = idx >> 7;
                    act_s[idx] = (gt == 2) ? ftanh(s) : fsig(s);
                }
            }
            __syncthreads();

            if (tid < 128) {
                float iv = act_s[tid];
                float fv = act_s[128 + tid];
                float gv = act_s[256 + tid];
                float ov = act_s[384 + tid];
                float c = fv*c_s[tid] + iv*gv;
                c_s[tid] = c;
                float h = ov*ftanh(c);
                __nv_bfloat16 hh = __float2bfloat16(h);
                __nv_bfloat16 hl = __float2bfloat16(h - __bfloat162float(hh));
                int u = u0 + (tid >> 4), b = tid & 15;
                g_h1hi[t & 3][b*Hz + u] = hh;
                g_h1lo[t & 3][b*Hz + u] = hl;
                hs1[((size_t)(b*Sz + t))*Hz + u] = h;
            }
            __syncthreads();
            if (tid == 0) arrive(ctr1);
        }
    }
}

// ------------------------------------------------------------------
extern "C" void kernel_launch(void* const* d_in, const int* in_sizes, int n_in,
                              void* d_out, int out_size)
{
    const int*   src   = (const int*)  d_in[0];
    const float* w_emb = (const float*)d_in[1];
    const float* b_emb = (const float*)d_in[2];
    const float* w_ih0 = (const float*)d_in[3];
    const float* w_hh0 = (const float*)d_in[4];
    const float* b_ih0 = (const float*)d_in[5];
    const float* b_hh0 = (const float*)d_in[6];
    const float* w_ih1 = (const float*)d_in[7];
    const float* w_hh1 = (const float*)d_in[8];
    const float* b_ih1 = (const float*)d_in[9];
    const float* b_hh1 = (const float*)d_in[10];
    const float* w1    = (const float*)d_in[11];
    const float* b1    = (const float*)d_in[12];
    const float* w2    = (const float*)d_in[13];
    const float* b2    = (const float*)d_in[14];
    float* out = (float*)d_out;

    float *emb, *xp, *hs1, *hid;
    cudaGetSymbolAddress((void**)&emb, g_emb);
    cudaGetSymbolAddress((void**)&xp,  g_xproj);
    cudaGetSymbolAddress((void**)&hs1, g_hs1);
    cudaGetSymbolAddress((void**)&hid, g_hid);

    const int DSMEM = 131072 + 2*16*HP*2 + (2048 + 1024 + 256)*4;
    cudaFuncSetAttribute(lstm_fused, cudaFuncAttributeMaxDynamicSharedMemorySize,
                         DSMEM);

    const int M = Bz * Sz;  // 8192

    embed_kernel<<<(M*Hz + 255)/256, 256>>>(src, w_emb, b_emb);
    reset_kernel<<<1, 64>>>();

    gemm_tf32<<<dim3(Gz/128, M/128), 256>>>(emb, w_ih0, b_ih0, b_hh0, xp,
                                            M, Gz, Hz, 0);

    lstm_fused<<<96, 256, DSMEM>>>(xp, w_hh0, w_ih1, w_hh1, b_ih1, b_hh1, hs1);

    gemm_tf32<<<dim3(1, M/128), 256>>>(hs1, w1, b1, nullptr, hid,
                                       M, 128, Hz, 1);

    gemm_tf32<<<dim3((Vz + 127)/128, M/128), 256>>>(hid, w2, b2, nullptr, out,
                                                    M, Vz, 128, 0);
}

// round 12
// speedup vs baseline: 1.4991x; 1.0276x over previous
#include <cuda_runtime.h>
#include <cuda_bf16.h>
#include <math.h>

#define Bz 16
#define Sz 512
#define Hz 512
#define Vz 10000
#define Gz 2048
#define HP 1032

// ---- scratch (static device globals) ----
__device__ float g_emb [Bz*Sz*Hz];
__device__ float g_xproj[Bz*Sz*Gz];
__device__ float g_hs1 [Bz*Sz*Hz];
__device__ float g_hid [Bz*Sz*128];
__device__ __align__(16) __nv_bfloat16 g_h0hi[4][Bz*Hz];
__device__ __align__(16) __nv_bfloat16 g_h0lo[4][Bz*Hz];
__device__ __align__(16) __nv_bfloat16 g_h1hi[4][Bz*Hz];
__device__ __align__(16) __nv_bfloat16 g_h1lo[4][Bz*Hz];
__device__ unsigned g_sync[64];   // ctr0 @0, ctr1 @32 (separate lines)

// ------------------------------------------------------------------
__global__ void reset_kernel() {
    if (threadIdx.x < 64) g_sync[threadIdx.x] = 0u;
}

__global__ void embed_kernel(const int* __restrict__ src,
                             const float* __restrict__ w_emb,
                             const float* __restrict__ b_emb)
{
    int idx = blockIdx.x * 256 + threadIdx.x;
    if (idx >= Bz*Sz*Hz) return;
    int h  = idx & (Hz-1);
    int bs = idx >> 9;
    int v  = src[bs];
    g_emb[idx] = w_emb[h*Vz + v] + b_emb[h];
}

// ------------------------------------------------------------------
// tf32 tensor-core GEMM (proven R4, unchanged).
__device__ __forceinline__ unsigned f2tf(float f) {
    unsigned u;
    asm("cvt.rna.tf32.f32 %0, %1;" : "=r"(u) : "f"(f));
    return u;
}
__device__ __forceinline__ void mma_tf32(float* d, const unsigned* a,
                                         const unsigned* b) {
    asm("mma.sync.aligned.m16n8k8.row.col.f32.tf32.tf32.f32 "
        "{%0,%1,%2,%3}, {%4,%5,%6,%7}, {%8,%9}, {%0,%1,%2,%3};"
        : "+f"(d[0]), "+f"(d[1]), "+f"(d[2]), "+f"(d[3])
        : "r"(a[0]), "r"(a[1]), "r"(a[2]), "r"(a[3]),
          "r"(b[0]), "r"(b[1]));
}

__global__ void __launch_bounds__(256)
gemm_tf32(const float* __restrict__ A, const float* __restrict__ B,
          const float* __restrict__ bias, const float* __restrict__ bias2,
          float* __restrict__ C, int M, int N, int K, int relu)
{
    __shared__ unsigned As[8*4*4*32];
    __shared__ unsigned Bs[16*4*2*32];

    const int tid = threadIdx.x;
    const int n0 = blockIdx.x * 128;
    const int m0 = blockIdx.y * 128;

    const int lm = tid >> 1;
    const int lk = (tid & 1) * 16;
    const float* Ap = A + (size_t)(m0 + lm) * K + lk;
    const float* Bp = B + (size_t)(n0 + lm) * K + lk;
    const bool bval = (n0 + lm) < N;

    const int warp = tid >> 5;
    const int lane = tid & 31;
    const int wm = warp >> 2;
    const int wn = warp & 3;

    float acc[4][4][4];
#pragma unroll
    for (int i = 0; i < 4; i++)
#pragma unroll
        for (int j = 0; j < 4; j++)
#pragma unroll
            for (int r = 0; r < 4; r++) acc[i][j][r] = 0.f;

    float4 a_r[4], b_r[4];
    const float4 z4 = make_float4(0.f, 0.f, 0.f, 0.f);
#pragma unroll
    for (int j = 0; j < 4; j++) {
        a_r[j] = *(const float4*)(Ap + 4*j);
        b_r[j] = bval ? *(const float4*)(Bp + 4*j) : z4;
    }

    const int mt_s = lm >> 4, r_s = lm & 15;
    const int nt_s = lm >> 3, ln_s = lm & 7;
    const int nch = K >> 5;

    for (int ch = 0; ch < nch; ch++) {
        __syncthreads();
#pragma unroll
        for (int j = 0; j < 4; j++) {
            int kc = lk + 4*j;
            int ks = kc >> 3;
            int cr = (kc & 7) >> 2;
            uint4 av = make_uint4(f2tf(a_r[j].x), f2tf(a_r[j].y),
                                  f2tf(a_r[j].z), f2tf(a_r[j].w));
            *(uint4*)&As[(((mt_s*4 + ks)*4) + cr*2 + (r_s >> 3))*32 + (r_s & 7)*4] = av;
            uint4 bv = make_uint4(f2tf(b_r[j].x), f2tf(b_r[j].y),
                                  f2tf(b_r[j].z), f2tf(b_r[j].w));
            *(uint4*)&Bs[(((nt_s*4 + ks)*2) + cr)*32 + ln_s*4] = bv;
        }
        __syncthreads();

        if (ch + 1 < nch) {
            const float* ap = Ap + (ch + 1)*32;
            const float* bp = Bp + (ch + 1)*32;
#pragma unroll
            for (int j = 0; j < 4; j++) {
                a_r[j] = *(const float4*)(ap + 4*j);
                b_r[j] = bval ? *(const float4*)(bp + 4*j) : z4;
            }
        }

#pragma unroll
        for (int ks = 0; ks < 4; ks++) {
            unsigned af[4][4];
#pragma unroll
            for (int mi = 0; mi < 4; mi++) {
                int base = (((wm*4 + mi)*4 + ks)*4)*32 + lane;
                af[mi][0] = As[base];
                af[mi][1] = As[base + 32];
                af[mi][2] = As[base + 64];
                af[mi][3] = As[base + 96];
            }
#pragma unroll
            for (int ni = 0; ni < 4; ni++) {
                int bb = (((wn*4 + ni)*4 + ks)*2)*32 + lane;
                unsigned bf[2] = { Bs[bb], Bs[bb + 32] };
#pragma unroll
                for (int mi = 0; mi < 4; mi++)
                    mma_tf32(acc[mi][ni], af[mi], bf);
            }
        }
    }

    const int g  = lane >> 2;
    const int tg = lane & 3;
#pragma unroll
    for (int ni = 0; ni < 4; ni++) {
        int ncol = n0 + wn*32 + ni*8 + tg*2;
        if (ncol < N) {
            float bb0 = bias[ncol]   + (bias2 ? bias2[ncol]   : 0.f);
            float bb1 = bias[ncol+1] + (bias2 ? bias2[ncol+1] : 0.f);
#pragma unroll
            for (int mi = 0; mi < 4; mi++) {
                int mrow = m0 + wm*64 + mi*16 + g;
                float2 v0 = make_float2(acc[mi][ni][0] + bb0,
                                        acc[mi][ni][1] + bb1);
                float2 v1 = make_float2(acc[mi][ni][2] + bb0,
                                        acc[mi][ni][3] + bb1);
                if (relu) {
                    v0.x = fmaxf(v0.x, 0.f); v0.y = fmaxf(v0.y, 0.f);
                    v1.x = fmaxf(v1.x, 0.f); v1.y = fmaxf(v1.y, 0.f);
                }
                *(float2*)(C + (size_t)mrow * N + ncol)       = v0;
                *(float2*)(C + (size_t)(mrow + 8) * N + ncol) = v1;
            }
        }
    }
}

// ------------------------------------------------------------------
__device__ __forceinline__ void poll_ge(unsigned* p, unsigned tgt) {
    unsigned v;
    do {
        asm volatile("ld.acquire.gpu.global.u32 %0, [%1];"
                     : "=r"(v) : "l"(p) : "memory");
    } while (v < tgt);
}
__device__ __forceinline__ void arrive(unsigned* p) {
    asm volatile("red.release.gpu.global.add.u32 [%0], 1;"
                 :: "l"(p) : "memory");
}

__device__ __forceinline__ unsigned pack_bf2(__nv_bfloat16 a, __nv_bfloat16 b) {
    return ((unsigned)__bfloat16_as_ushort(b) << 16) | __bfloat16_as_ushort(a);
}
__device__ __forceinline__ void mma_bf16(float* d, const unsigned* a,
                                         unsigned b0, unsigned b1) {
    asm("mma.sync.aligned.m16n8k16.row.col.f32.bf16.bf16.f32 "
        "{%0,%1,%2,%3}, {%4,%5,%6,%7}, {%8,%9}, {%0,%1,%2,%3};"
        : "+f"(d[0]), "+f"(d[1]), "+f"(d[2]), "+f"(d[3])
        : "r"(a[0]), "r"(a[1]), "r"(a[2]), "r"(a[3]), "r"(b0), "r"(b1));
}
__device__ __forceinline__ void ldsm_x4(unsigned& r0, unsigned& r1,
                                        unsigned& r2, unsigned& r3,
                                        unsigned addr) {
    asm volatile("ldmatrix.sync.aligned.m8n8.x4.shared.b16 {%0,%1,%2,%3}, [%4];"
                 : "=r"(r0), "=r"(r1), "=r"(r2), "=r"(r3) : "r"(addr));
}
__device__ __forceinline__ unsigned smem_u32(const void* p) {
    return (unsigned)__cvta_generic_to_shared(p);
}
__device__ __forceinline__ float fsig(float x) {
    return __fdividef(1.f, 1.f + __expf(-x));
}
__device__ __forceinline__ float ftanh(float x) {
    float xc = fminf(fmaxf(x, -15.f), 15.f);
    float e = __expf(2.f * xc);
    return __fdividef(e - 1.f, e + 1.f);
}

// ------------------------------------------------------------------
// Fused 2-layer wavefront LSTM (R11 + fused reduce/act/cell-update).
// 96 CTAs: 32 L0 (16 units), 64 L1 (8 units, k=1024 concat). Decoupled
// counters, 4-deep h buffers, reg-resident A frags, ldmatrix B frags.
__global__ void __launch_bounds__(256)
lstm_fused(const float* __restrict__ xproj,
           const float* __restrict__ w_hh0,
           const float* __restrict__ w_ih1,
           const float* __restrict__ w_hh1,
           const float* __restrict__ b_ih1,
           const float* __restrict__ b_hh1,
           float* __restrict__ hs1)
{
    extern __shared__ __align__(16) unsigned char dyn[];
    float* w_stage = (float*)dyn;                          // 128KB (init only)
    __nv_bfloat16* Hhi_s = (__nv_bfloat16*)(dyn + 131072); // [16][HP]
    __nv_bfloat16* Hlo_s = Hhi_s + 16*HP;
    float* part  = (float*)(Hlo_s + 16*HP);                // [2048]
    float* act_s = part + 2048;                            // [1024] (unused)
    float* c_s   = act_s + 1024;                           // [256]

    const int tid  = threadIdx.x;
    const int bid  = blockIdx.x;
    const bool is0 = bid < 32;
    const int u0   = is0 ? bid*16 : (bid-32)*8;
    const int warp = tid >> 5;
    const int lane = tid & 31;
    const int g    = lane >> 2;
    const int tg   = lane & 3;
    unsigned* ctr0 = g_sync;
    unsigned* ctr1 = g_sync + 32;

    const int Kw = is0 ? 512 : 1024;

    // ---- stage weights coalesced into SMEM ----
    for (int idx4 = tid; idx4 < 8192; idx4 += 256) {
        int row, k;
        if (is0) { row = idx4 >> 7; k = (idx4 & 127) * 4; }
        else     { row = idx4 >> 8; k = (idx4 & 255) * 4; }
        const float* W;
        int gate, koff;
        if (is0) {
            gate = (row >> 4)*Hz + u0 + (row & 15);
            W = w_hh0; koff = k;
        } else {
            gate = (row >> 3)*Hz + u0 + (row & 7);
            if (k < Hz) { W = w_ih1; koff = k; }
            else        { W = w_hh1; koff = k - Hz; }
        }
        *(float4*)(w_stage + row*Kw + k) =
            *(const float4*)(W + (size_t)gate*Hz + koff);
    }
    __syncthreads();

    // ---- A fragments -> registers (split-bf16); compile-time bounds ----
    const int mt = is0 ? (warp & 3) : (warp & 1);
    const int kg = is0 ? (warp >> 2) : (warp >> 1);
    unsigned Ahi[16][4], Alo[16][4];
#pragma unroll
    for (int kk = 0; kk < 16; kk++) {
        int ks = kg*16 + kk;
#pragma unroll
        for (int r = 0; r < 4; r++) {
            int row = mt*16 + g + (r & 1)*8;
            int k   = ks*16 + 2*tg + (r >> 1)*8;
            float w0 = w_stage[row*Kw + k];
            float w1 = w_stage[row*Kw + k + 1];
            __nv_bfloat16 h0 = __float2bfloat16(w0);
            __nv_bfloat16 h1 = __float2bfloat16(w1);
            __nv_bfloat16 l0 = __float2bfloat16(w0 - __bfloat162float(h0));
            __nv_bfloat16 l1 = __float2bfloat16(w1 - __bfloat162float(h1));
            Ahi[kk][r] = pack_bf2(h0, h1);
            Alo[kk][r] = pack_bf2(l0, l1);
        }
    }

    // ---- ldmatrix lane addressing (B frags) ----
    const int mrow = lane >> 3, rr = lane & 7;
    const int nn   = ((mrow >> 1) << 3) + rr;
    const int kof  = (mrow & 1) * 8;
    const unsigned bhi_base = smem_u32(Hhi_s) + (nn*HP + kof)*2;
    const unsigned blo_base = bhi_base + 16*HP*2;

    // ---- init state + base (xproj / bias per (u,b) thread, 4 gates) ----
    float base_r[4];
    const __nv_bfloat16 zb = __float2bfloat16(0.f);
    if (is0) {
        c_s[tid] = 0.f;
        int u = u0 + (tid >> 4), b = tid & 15;
        g_h0hi[3][b*Hz + u] = zb;
        g_h0lo[3][b*Hz + u] = zb;
#pragma unroll
        for (int j = 0; j < 4; j++) {
            int idx = tid + 256*j;
            int lg = idx >> 4, b2 = idx & 15;
            int gate = (lg >> 4)*Hz + u0 + (lg & 15);
            base_r[j] = xproj[((size_t)(b2 << 9))*Gz + gate];
        }
    } else {
        if (tid < 128) {
            c_s[tid] = 0.f;
            int u = u0 + (tid >> 4), b = tid & 15;
            g_h1hi[3][b*Hz + u] = zb;
            g_h1lo[3][b*Hz + u] = zb;
            int ul = tid >> 4;
#pragma unroll
            for (int j = 0; j < 4; j++) {
                int gate = j*Hz + u0 + ul;
                base_r[j] = b_ih1[gate] + b_hh1[gate];
            }
        }
    }
    __syncthreads();
    if (tid == 0) arrive(is0 ? ctr0 : ctr1);

    if (is0) {
        // ============ LAYER 0: rounds r = 0..511 ============
        for (int r = 0; r < Sz; r++) {
            if (tid < 2) {
                unsigned* p  = (tid == 0) ? ctr0 : ctr1;
                unsigned tgt = (tid == 0) ? 32u*(r+1)
                             : (r >= 3 ? 64u*(r-2) : 0u);
                if (tgt) poll_ge(p, tgt);
            }
            __syncthreads();

            {   // stage h0_{r-1} (slot (r+3)&3)
                const uint4* ghi = (const uint4*)g_h0hi[(r+3)&3];
                const uint4* glo = (const uint4*)g_h0lo[(r+3)&3];
#pragma unroll
                for (int i = 0; i < 4; i++) {
                    int idx = tid + 256*i;
                    int b = idx >> 6, uo = (idx & 63)*8;
                    uint4 vh = __ldcg(ghi + idx);
                    uint4 vl = __ldcg(glo + idx);
                    *(uint4*)(Hhi_s + b*HP + uo) = vh;
                    *(uint4*)(Hlo_s + b*HP + uo) = vl;
                }
            }
            float nxt[4];
            {
                int tn = (r + 1 < Sz) ? r + 1 : r;
#pragma unroll
                for (int j = 0; j < 4; j++) {
                    int idx = tid + 256*j;
                    int lg = idx >> 4, b2 = idx & 15;
                    int gate = (lg >> 4)*Hz + u0 + (lg & 15);
                    nxt[j] = xproj[((size_t)((b2 << 9) | tn))*Gz + gate];
                }
            }
            __syncthreads();

            float aA0[4]={0,0,0,0}, aB0[4]={0,0,0,0}, aC0[4]={0,0,0,0};
            float aA1[4]={0,0,0,0}, aB1[4]={0,0,0,0}, aC1[4]={0,0,0,0};
#pragma unroll
            for (int kk = 0; kk < 16; kk++) {
                int ks = kg*16 + kk;
                unsigned bh0,bh1,bh2,bh3, bl0,bl1,bl2,bl3;
                ldsm_x4(bh0,bh1,bh2,bh3, bhi_base + ks*32);
                ldsm_x4(bl0,bl1,bl2,bl3, blo_base + ks*32);
                mma_bf16(aA0, Ahi[kk], bh0, bh1);
                mma_bf16(aA1, Ahi[kk], bh2, bh3);
                mma_bf16(aB0, Ahi[kk], bl0, bl1);
                mma_bf16(aB1, Ahi[kk], bl2, bl3);
                mma_bf16(aC0, Alo[kk], bh0, bh1);
                mma_bf16(aC1, Alo[kk], bh2, bh3);
            }
            float acc0[4], acc1[4];
#pragma unroll
            for (int q = 0; q < 4; q++) {
                acc0[q] = aA0[q] + aB0[q] + aC0[q];
                acc1[q] = aA1[q] + aB1[q] + aC1[q];
            }
            float* pw = part + kg*1024;
            *(float2*)&pw[(mt*16 + g)*16 + 2*tg]         = make_float2(acc0[0], acc0[1]);
            *(float2*)&pw[(mt*16 + g + 8)*16 + 2*tg]     = make_float2(acc0[2], acc0[3]);
            *(float2*)&pw[(mt*16 + g)*16 + 8 + 2*tg]     = make_float2(acc1[0], acc1[1]);
            *(float2*)&pw[(mt*16 + g + 8)*16 + 8 + 2*tg] = make_float2(acc1[2], acc1[3]);
            __syncthreads();

            {   // fused reduce + activation + cell update (thread = (u,b))
                float acts[4];
#pragma unroll
                for (int j = 0; j < 4; j++) {
                    float s = base_r[j] + part[j*256 + tid]
                            + part[1024 + j*256 + tid];
                    acts[j] = (j == 2) ? ftanh(s) : fsig(s);
                }
                float c = acts[1]*c_s[tid] + acts[0]*acts[2];
                c_s[tid] = c;
                float h = acts[3]*ftanh(c);
                __nv_bfloat16 hh = __float2bfloat16(h);
                __nv_bfloat16 hl = __float2bfloat16(h - __bfloat162float(hh));
                int u = u0 + (tid >> 4), b = tid & 15;
                g_h0hi[r & 3][b*Hz + u] = hh;
                g_h0lo[r & 3][b*Hz + u] = hl;
            }
#pragma unroll
            for (int j = 0; j < 4; j++) base_r[j] = nxt[j];
            __syncthreads();
            if (tid == 0) arrive(ctr0);
        }
    } else {
        // ============ LAYER 1: rounds r = 1..512 ============
        for (int r = 1; r <= Sz; r++) {
            const int t = r - 1;
            if (tid < 2) {
                unsigned* p  = (tid == 0) ? ctr0 : ctr1;
                unsigned tgt = (tid == 0) ? 32u*(r+1) : 64u*r;
                poll_ge(p, tgt);
            }
            __syncthreads();

            // stage h0_t (slot t&3) -> cols [0,512); h1_{t-1} (slot (t+3)&3) -> [512,1024)
            {
                const uint4* g0h = (const uint4*)g_h0hi[t & 3];
                const uint4* g0l = (const uint4*)g_h0lo[t & 3];
                const uint4* g1h = (const uint4*)g_h1hi[(t+3) & 3];
                const uint4* g1l = (const uint4*)g_h1lo[(t+3) & 3];
#pragma unroll
                for (int i = 0; i < 4; i++) {
                    int idx = tid + 256*i;
                    int b = idx >> 6, uo = (idx & 63)*8;
                    uint4 vh = __ldcg(g0h + idx);
                    uint4 vl = __ldcg(g0l + idx);
                    *(uint4*)(Hhi_s + b*HP + uo) = vh;
                    *(uint4*)(Hlo_s + b*HP + uo) = vl;
                    uint4 wh = __ldcg(g1h + idx);
                    uint4 wl = __ldcg(g1l + idx);
                    *(uint4*)(Hhi_s + b*HP + 512 + uo) = wh;
                    *(uint4*)(Hlo_s + b*HP + 512 + uo) = wl;
                }
            }
            __syncthreads();

            float aA0[4]={0,0,0,0}, aB0[4]={0,0,0,0}, aC0[4]={0,0,0,0};
            float aA1[4]={0,0,0,0}, aB1[4]={0,0,0,0}, aC1[4]={0,0,0,0};
#pragma unroll
            for (int kk = 0; kk < 16; kk++) {
                int ks = kg*16 + kk;
                unsigned bh0,bh1,bh2,bh3, bl0,bl1,bl2,bl3;
                ldsm_x4(bh0,bh1,bh2,bh3, bhi_base + ks*32);
                ldsm_x4(bl0,bl1,bl2,bl3, blo_base + ks*32);
                mma_bf16(aA0, Ahi[kk], bh0, bh1);
                mma_bf16(aA1, Ahi[kk], bh2, bh3);
                mma_bf16(aB0, Ahi[kk], bl0, bl1);
                mma_bf16(aB1, Ahi[kk], bl2, bl3);
                mma_bf16(aC0, Alo[kk], bh0, bh1);
                mma_bf16(aC1, Alo[kk], bh2, bh3);
            }
            float acc0[4], acc1[4];
#pragma unroll
            for (int q = 0; q < 4; q++) {
                acc0[q] = aA0[q] + aB0[q] + aC0[q];
                acc1[q] = aA1[q] + aB1[q] + aC1[q];
            }
            float* pw = part + kg*512;
            *(float2*)&pw[(mt*16 + g)*16 + 2*tg]         = make_float2(acc0[0], acc0[1]);
            *(float2*)&pw[(mt*16 + g + 8)*16 + 2*tg]     = make_float2(acc0[2], acc0[3]);
            *(float2*)&pw[(mt*16 + g)*16 + 8 + 2*tg]     = make_float2(acc1[0], acc1[1]);
            *(float2*)&pw[(mt*16 + g + 8)*16 + 8 + 2*tg] = make_float2(acc1[2], acc1[3]);
            __syncthreads();

            float h_out = 0.f;
            if (tid < 128) {   // fused reduce + activation + cell update
                float acts[4];
#pragma unroll
                for (int j = 0; j < 4; j++) {
                    float s = base_r[j] + part[j*128 + tid]
                            + part[512  + j*128 + tid]
                            + part[1024 + j*128 + tid]
                            + part[1536 + j*128 + tid];
                    acts[j] = (j == 2) ? ftanh(s) : fsig(s);
                }
                float c = acts[1]*c_s[tid] + acts[0]*acts[2];
                c_s[tid] = c;
                h_out = acts[3]*ftanh(c);
                __nv_bfloat16 hh = __float2bfloat16(h_out);
                __nv_bfloat16 hl = __float2bfloat16(h_out - __bfloat162float(hh));
                int u = u0 + (tid >> 4), b = tid & 15;
                g_h1hi[t & 3][b*Hz + u] = hh;
                g_h1lo[t & 3][b*Hz + u] = hl;
            }
            __syncthreads();
            if (tid == 0) arrive(ctr1);
            if (tid < 128) {   // hs1 store off the inter-CTA critical path
                int u = u0 + (tid >> 4), b = tid & 15;
                hs1[((size_t)(b*Sz + t))*Hz + u] = h_out;
            }
        }
    }
}

// ------------------------------------------------------------------
extern "C" void kernel_launch(void* const* d_in, const int* in_sizes, int n_in,
                              void* d_out, int out_size)
{
    const int*   src   = (const int*)  d_in[0];
    const float* w_emb = (const float*)d_in[1];
    const float* b_emb = (const float*)d_in[2];
    const float* w_ih0 = (const float*)d_in[3];
    const float* w_hh0 = (const float*)d_in[4];
    const float* b_ih0 = (const float*)d_in[5];
    const float* b_hh0 = (const float*)d_in[6];
    const float* w_ih1 = (const float*)d_in[7];
    const float* w_hh1 = (const float*)d_in[8];
    const float* b_ih1 = (const float*)d_in[9];
    const float* b_hh1 = (const float*)d_in[10];
    const float* w1    = (const float*)d_in[11];
    const float* b1    = (const float*)d_in[12];
    const float* w2    = (const float*)d_in[13];
    const float* b2    = (const float*)d_in[14];
    float* out = (float*)d_out;

    float *emb, *xp, *hs1, *hid;
    cudaGetSymbolAddress((void**)&emb, g_emb);
    cudaGetSymbolAddress((void**)&xp,  g_xproj);
    cudaGetSymbolAddress((void**)&hs1, g_hs1);
    cudaGetSymbolAddress((void**)&hid, g_hid);

    const int DSMEM = 131072 + 2*16*HP*2 + (2048 + 1024 + 256)*4;
    cudaFuncSetAttribute(lstm_fused, cudaFuncAttributeMaxDynamicSharedMemorySize,
                         DSMEM);

    const int M = Bz * Sz;  // 8192

    embed_kernel<<<(M*Hz + 255)/256, 256>>>(src, w_emb, b_emb);
    reset_kernel<<<1, 64>>>();

    gemm_tf32<<<dim3(Gz/128, M/128), 256>>>(emb, w_ih0, b_ih0, b_hh0, xp,
                                            M, Gz, Hz, 0);

    lstm_fused<<<96, 256, DSMEM>>>(xp, w_hh0, w_ih1, w_hh1, b_ih1, b_hh1, hs1);

    gemm_tf32<<<dim3(1, M/128), 256>>>(hs1, w1, b1, nullptr, hid,
                                       M, 128, Hz, 1);

    gemm_tf32<<<dim3((Vz + 127)/128, M/128), 256>>>(hid, w2, b2, nullptr, out,
                                                    M, Vz, 128, 0);
}